// round 1
// baseline (speedup 1.0000x reference)
#include <cuda_runtime.h>
#include <cuda_bf16.h>

// ---------------------------------------------------------------------------
// Problem constants (match reference)
// ---------------------------------------------------------------------------
#define MAX_NODES 50000
#define MAX_EDGES 800000
#define NODE_DIM  64
#define GNN_H     128
#define GNN_DIM   64
#define NB        128   // batch of graphs
#define HIDDEN    256
#define ACTION_DIM 8

// ---------------------------------------------------------------------------
// Device scratch (static globals; allocation-free per harness rules)
// ---------------------------------------------------------------------------
__device__ float g_bufP[MAX_NODES * GNN_H];   // P (layer1 128 / layer2 64 cols)
__device__ float g_bufQ[MAX_NODES * GNN_H];   // Q
__device__ float g_bufS[MAX_NODES * GNN_H];   // aggregated mean(relu(z))
__device__ float g_bufH[MAX_NODES * GNN_H];   // layer output h
__device__ int   g_deg[MAX_NODES];
__device__ int   g_cursor[MAX_NODES];
__device__ int   g_rowptr[MAX_NODES];
__device__ int   g_csr[MAX_EDGES];
__device__ float g_gsum[NB * GNN_DIM];
__device__ int   g_gcnt[NB];

// ---------------------------------------------------------------------------
// CSR build
// ---------------------------------------------------------------------------
__global__ void hist_kernel(const int* __restrict__ dst, int* __restrict__ deg, int n_edges)
{
    int e = blockIdx.x * blockDim.x + threadIdx.x;
    if (e < n_edges) atomicAdd(&deg[dst[e]], 1);
}

__global__ void scan_kernel(const int* __restrict__ deg, int* __restrict__ row_ptr, int n)
{
    __shared__ int part[1024];
    int t = threadIdx.x;
    int ch = (n + 1023) / 1024;
    int lo = t * ch;
    int hi = lo + ch; if (hi > n) hi = n;
    int s = 0;
    for (int i = lo; i < hi; i++) s += deg[i];
    part[t] = s;
    __syncthreads();
    // inclusive Hillis-Steele scan over 1024 partials
    for (int off = 1; off < 1024; off <<= 1) {
        int v = (t >= off) ? part[t - off] : 0;
        __syncthreads();
        part[t] += v;
        __syncthreads();
    }
    int run = (t == 0) ? 0 : part[t - 1];
    for (int i = lo; i < hi; i++) { row_ptr[i] = run; run += deg[i]; }
}

__global__ void fill_kernel(const int* __restrict__ src, const int* __restrict__ dst,
                            const int* __restrict__ row_ptr, int* __restrict__ cursor,
                            int* __restrict__ csr, int n_edges)
{
    int e = blockIdx.x * blockDim.x + threadIdx.x;
    if (e >= n_edges) return;
    int d = dst[e];
    int pos = atomicAdd(&cursor[d], 1);
    csr[row_ptr[d] + pos] = src[e];
}

// ---------------------------------------------------------------------------
// Tiled SGEMM: C[M,N] = A[M,K] @ W[K,N]  (+bias, +relu, +deg-mask via flags)
// BM=64 BN=64 BK=32, 256 threads, 4x4 microtile.
// flags: 1 = add bias, 2 = relu, 4 = zero rows with deg==0
// ---------------------------------------------------------------------------
#define FLAG_BIAS 1
#define FLAG_RELU 2
#define FLAG_MASK 4

__global__ __launch_bounds__(256) void sgemm_kernel(
    const float* __restrict__ A, const float* __restrict__ W,
    const float* __restrict__ bias, const int* __restrict__ deg,
    float* __restrict__ C,
    int M, int N, int K, int lda, int ldw, int ldc, int flags)
{
    __shared__ float As[32][65];   // [k][m], +1 pad -> conflict-free transpose stores
    __shared__ float Ws[32][64];   // [k][n]

    const int tid = threadIdx.x;
    const int bm = blockIdx.x * 64;
    const int bn = blockIdx.y * 64;
    const int tx = tid & 15;       // 0..15 -> 4 cols each
    const int ty = tid >> 4;       // 0..15 -> 4 rows each

    const int arow  = tid >> 3;        // 0..31
    const int acol4 = (tid & 7) * 4;   // 0..28
    const int wrow  = tid >> 4;        // 0..15
    const int wcol4 = (tid & 15) * 4;  // 0..60

    float acc[4][4] = {};

    for (int kt = 0; kt < K; kt += 32) {
        #pragma unroll
        for (int r = 0; r < 2; r++) {
            int row  = arow + r * 32;
            int grow = bm + row;
            float4 v = make_float4(0.f, 0.f, 0.f, 0.f);
            if (grow < M) v = *(const float4*)(A + (size_t)grow * lda + kt + acol4);
            As[acol4 + 0][row] = v.x;
            As[acol4 + 1][row] = v.y;
            As[acol4 + 2][row] = v.z;
            As[acol4 + 3][row] = v.w;
        }
        #pragma unroll
        for (int r = 0; r < 2; r++) {
            int row = wrow + r * 16;
            float4 v = *(const float4*)(W + (size_t)(kt + row) * ldw + bn + wcol4);
            *(float4*)&Ws[row][wcol4] = v;
        }
        __syncthreads();
        #pragma unroll
        for (int k = 0; k < 32; k++) {
            float a0 = As[k][ty * 4 + 0];
            float a1 = As[k][ty * 4 + 1];
            float a2 = As[k][ty * 4 + 2];
            float a3 = As[k][ty * 4 + 3];
            float4 b = *(const float4*)&Ws[k][tx * 4];
            acc[0][0] += a0 * b.x; acc[0][1] += a0 * b.y; acc[0][2] += a0 * b.z; acc[0][3] += a0 * b.w;
            acc[1][0] += a1 * b.x; acc[1][1] += a1 * b.y; acc[1][2] += a1 * b.z; acc[1][3] += a1 * b.w;
            acc[2][0] += a2 * b.x; acc[2][1] += a2 * b.y; acc[2][2] += a2 * b.z; acc[2][3] += a2 * b.w;
            acc[3][0] += a3 * b.x; acc[3][1] += a3 * b.y; acc[3][2] += a3 * b.z; acc[3][3] += a3 * b.w;
        }
        __syncthreads();
    }

    #pragma unroll
    for (int i = 0; i < 4; i++) {
        int grow = bm + ty * 4 + i;
        if (grow >= M) continue;
        bool zero = (flags & FLAG_MASK) && (deg[grow] == 0);
        #pragma unroll
        for (int j = 0; j < 4; j++) {
            int gcol = bn + tx * 4 + j;
            float v = acc[i][j];
            if (flags & FLAG_BIAS) v += bias[gcol];
            if (flags & FLAG_RELU) v = fmaxf(v, 0.f);
            if (zero) v = 0.f;
            C[(size_t)grow * ldc + gcol] = v;
        }
    }
}

// ---------------------------------------------------------------------------
// Edge gather-reduce: S[n] = mean_{e: dst=n} relu(P[n] + Q[src_e])
// LANES threads cooperate on one node; each owns a float4 (FEAT = LANES*4).
// ---------------------------------------------------------------------------
template <int LANES>
__global__ void gather_kernel(const float* __restrict__ P, const float* __restrict__ Q,
                              const int* __restrict__ row_ptr, const int* __restrict__ deg,
                              const int* __restrict__ csr,
                              float* __restrict__ S, int n_nodes)
{
    const int FEAT = LANES * 4;
    int gid  = blockIdx.x * blockDim.x + threadIdx.x;
    int node = gid / LANES;
    int sub  = gid % LANES;
    if (node >= n_nodes) return;

    float4 p = *(const float4*)(P + (size_t)node * FEAT + sub * 4);
    int start = row_ptr[node];
    int d     = deg[node];

    float4 acc = make_float4(0.f, 0.f, 0.f, 0.f);
    int s_next = (d > 0) ? csr[start] : 0;
    for (int i = 0; i < d; i++) {
        int s = s_next;
        if (i + 1 < d) s_next = csr[start + i + 1];
        float4 q = *(const float4*)(Q + (size_t)s * FEAT + sub * 4);
        acc.x += fmaxf(p.x + q.x, 0.f);
        acc.y += fmaxf(p.y + q.y, 0.f);
        acc.z += fmaxf(p.z + q.z, 0.f);
        acc.w += fmaxf(p.w + q.w, 0.f);
    }
    float inv = 1.0f / (float)(d > 0 ? d : 1);
    float4 o = make_float4(acc.x * inv, acc.y * inv, acc.z * inv, acc.w * inv);
    *(float4*)(S + (size_t)node * FEAT + sub * 4) = o;
}

// ---------------------------------------------------------------------------
// Graph pooling: atomic scatter of h2 into per-graph sums + counts
// ---------------------------------------------------------------------------
__global__ void pool_kernel(const float* __restrict__ H, const int* __restrict__ nb,
                            float* __restrict__ gsum, int* __restrict__ gcnt, int n_nodes)
{
    int gid  = blockIdx.x * blockDim.x + threadIdx.x;
    int node = gid >> 4;       // 16 float4 per node (64 feats)
    int f    = gid & 15;
    if (node >= n_nodes) return;
    int b = nb[node];
    float4 v = *(const float4*)(H + (size_t)node * GNN_DIM + f * 4);
    atomicAdd(&gsum[b * GNN_DIM + f * 4 + 0], v.x);
    atomicAdd(&gsum[b * GNN_DIM + f * 4 + 1], v.y);
    atomicAdd(&gsum[b * GNN_DIM + f * 4 + 2], v.z);
    atomicAdd(&gsum[b * GNN_DIM + f * 4 + 3], v.w);
    if (f == 0) atomicAdd(&gcnt[b], 1);
}

// ---------------------------------------------------------------------------
// Actor head: z = [state | graph_embed]; fc1-relu; fc2-relu; mean + clipped logstd
// One block (256 threads) per graph.
// ---------------------------------------------------------------------------
__global__ __launch_bounds__(256) void head_kernel(
    const float* __restrict__ state,
    const float* __restrict__ gsum, const int* __restrict__ gcnt,
    const float* __restrict__ fc1_w, const float* __restrict__ fc1_b,
    const float* __restrict__ fc2_w, const float* __restrict__ fc2_b,
    const float* __restrict__ mean_w, const float* __restrict__ mean_b,
    const float* __restrict__ ls_w, const float* __restrict__ ls_b,
    float* __restrict__ out, int n_graphs)
{
    __shared__ float z[128];
    __shared__ float h1[256];
    __shared__ float h2[256];
    int b = blockIdx.x;
    int t = threadIdx.x;
    if (b >= n_graphs) return;

    if (t < 64) {
        z[t] = state[b * 64 + t];
    } else if (t < 128) {
        float c = (float)gcnt[b];
        c = fmaxf(c, 1.f);
        z[t] = gsum[b * GNN_DIM + (t - 64)] / c;
    }
    __syncthreads();

    {
        float s = fc1_b[t];
        #pragma unroll 4
        for (int k = 0; k < 128; k++) s += z[k] * fc1_w[k * 256 + t];
        h1[t] = fmaxf(s, 0.f);
    }
    __syncthreads();
    {
        float s = fc2_b[t];
        #pragma unroll 4
        for (int k = 0; k < 256; k++) s += h1[k] * fc2_w[k * 256 + t];
        h2[t] = fmaxf(s, 0.f);
    }
    __syncthreads();

    if (t < ACTION_DIM) {
        float s = mean_b[t];
        #pragma unroll 4
        for (int k = 0; k < 256; k++) s += h2[k] * mean_w[k * ACTION_DIM + t];
        out[b * ACTION_DIM + t] = s;
    } else if (t < 2 * ACTION_DIM) {
        int j = t - ACTION_DIM;
        float s = ls_b[j];
        #pragma unroll 4
        for (int k = 0; k < 256; k++) s += h2[k] * ls_w[k * ACTION_DIM + j];
        s = fminf(fmaxf(s, -20.f), 2.f);
        out[n_graphs * ACTION_DIM + b * ACTION_DIM + j] = s;
    }
}

// ---------------------------------------------------------------------------
// Launch
// ---------------------------------------------------------------------------
extern "C" void kernel_launch(void* const* d_in, const int* in_sizes, int n_in,
                              void* d_out, int out_size)
{
    const float* state    = (const float*)d_in[0];
    const float* x        = (const float*)d_in[1];
    const int*   eidx     = (const int*)  d_in[2];
    const int*   nbatch   = (const int*)  d_in[3];
    const float* g1w1     = (const float*)d_in[4];
    const float* g1b1     = (const float*)d_in[5];
    const float* g1w2     = (const float*)d_in[6];
    const float* g1b2     = (const float*)d_in[7];
    const float* g2w1     = (const float*)d_in[8];
    const float* g2b1     = (const float*)d_in[9];
    const float* g2w2     = (const float*)d_in[10];
    const float* g2b2     = (const float*)d_in[11];
    const float* fc1_w    = (const float*)d_in[12];
    const float* fc1_b    = (const float*)d_in[13];
    const float* fc2_w    = (const float*)d_in[14];
    const float* fc2_b    = (const float*)d_in[15];
    const float* mean_w   = (const float*)d_in[16];
    const float* mean_b   = (const float*)d_in[17];
    const float* ls_w     = (const float*)d_in[18];
    const float* ls_b     = (const float*)d_in[19];
    float* out = (float*)d_out;

    const int n_graphs = in_sizes[0] / 64;
    const int n_nodes  = in_sizes[1] / NODE_DIM;
    const int n_edges  = in_sizes[2] / 2;
    const int* e_src = eidx;
    const int* e_dst = eidx + n_edges;

    float *bufP, *bufQ, *bufS, *bufH, *gsum;
    int *deg, *cursor, *rowptr, *csr, *gcnt;
    cudaGetSymbolAddress((void**)&bufP,   g_bufP);
    cudaGetSymbolAddress((void**)&bufQ,   g_bufQ);
    cudaGetSymbolAddress((void**)&bufS,   g_bufS);
    cudaGetSymbolAddress((void**)&bufH,   g_bufH);
    cudaGetSymbolAddress((void**)&deg,    g_deg);
    cudaGetSymbolAddress((void**)&cursor, g_cursor);
    cudaGetSymbolAddress((void**)&rowptr, g_rowptr);
    cudaGetSymbolAddress((void**)&csr,    g_csr);
    cudaGetSymbolAddress((void**)&gsum,   g_gsum);
    cudaGetSymbolAddress((void**)&gcnt,   g_gcnt);

    // ---- zero counters (graph-capturable async memsets) ----
    cudaMemsetAsync(deg,    0, n_nodes * sizeof(int));
    cudaMemsetAsync(cursor, 0, n_nodes * sizeof(int));
    cudaMemsetAsync(gsum,   0, n_graphs * GNN_DIM * sizeof(float));
    cudaMemsetAsync(gcnt,   0, n_graphs * sizeof(int));

    // ---- CSR build ----
    int eblocks = (n_edges + 255) / 256;
    hist_kernel<<<eblocks, 256>>>(e_dst, deg, n_edges);
    scan_kernel<<<1, 1024>>>(deg, rowptr, n_nodes);
    fill_kernel<<<eblocks, 256>>>(e_src, e_dst, rowptr, cursor, csr, n_edges);

    dim3 blk(256);
    int mb = (n_nodes + 63) / 64;

    // ---- GNN layer 1 ----
    // P = x @ W1[:64,:] + b1    [N,128]
    sgemm_kernel<<<dim3(mb, 2), blk>>>(x, g1w1,            g1b1, deg, bufP,
                                       n_nodes, 128, 64, 64, 128, 128, FLAG_BIAS);
    // Q = x @ W1[64:,:]         [N,128]
    sgemm_kernel<<<dim3(mb, 2), blk>>>(x, g1w1 + 64 * 128, g1b1, deg, bufQ,
                                       n_nodes, 128, 64, 64, 128, 128, 0);
    // S = mean_dst relu(P[dst]+Q[src])
    {
        int total = n_nodes * 32;
        gather_kernel<32><<<(total + 255) / 256, 256>>>(bufP, bufQ, rowptr, deg, csr, bufS, n_nodes);
    }
    // H1 = relu(S @ W2 + b2), masked (deg==0 -> 0)
    sgemm_kernel<<<dim3(mb, 2), blk>>>(bufS, g1w2, g1b2, deg, bufH,
                                       n_nodes, 128, 128, 128, 128, 128,
                                       FLAG_BIAS | FLAG_RELU | FLAG_MASK);

    // ---- GNN layer 2 ----
    // P2 = H1 @ W1[:128,:] + b1  [N,64]
    sgemm_kernel<<<dim3(mb, 1), blk>>>(bufH, g2w1,             g2b1, deg, bufP,
                                       n_nodes, 64, 128, 128, 64, 64, FLAG_BIAS);
    // Q2 = H1 @ W1[128:,:]       [N,64]
    sgemm_kernel<<<dim3(mb, 1), blk>>>(bufH, g2w1 + 128 * 64, g2b1, deg, bufQ,
                                       n_nodes, 64, 128, 128, 64, 64, 0);
    {
        int total = n_nodes * 16;
        gather_kernel<16><<<(total + 255) / 256, 256>>>(bufP, bufQ, rowptr, deg, csr, bufS, n_nodes);
    }
    // H2 = S2 @ W2 + b2, masked, no relu   [N,64]
    sgemm_kernel<<<dim3(mb, 1), blk>>>(bufS, g2w2, g2b2, deg, bufH,
                                       n_nodes, 64, 64, 64, 64, 64,
                                       FLAG_BIAS | FLAG_MASK);

    // ---- pooling ----
    {
        int total = n_nodes * 16;
        pool_kernel<<<(total + 255) / 256, 256>>>(bufH, nbatch, gsum, gcnt, n_nodes);
    }

    // ---- head ----
    head_kernel<<<n_graphs, 256>>>(state, gsum, gcnt,
                                   fc1_w, fc1_b, fc2_w, fc2_b,
                                   mean_w, mean_b, ls_w, ls_b,
                                   out, n_graphs);
}

// round 2
// speedup vs baseline: 1.2059x; 1.2059x over previous
#include <cuda_runtime.h>
#include <cuda_fp16.h>
#include <cstdint>

// ---------------------------------------------------------------------------
// Problem constants
// ---------------------------------------------------------------------------
#define MAX_NODES 50000
#define MAX_EDGES 800000
#define NODE_DIM  64
#define GNN_H     128
#define GNN_DIM   64
#define NB        128
#define HIDDEN    256
#define ACTION_DIM 8

// ---------------------------------------------------------------------------
// Device scratch
// ---------------------------------------------------------------------------
__device__ float  g_bufP[MAX_NODES * GNN_H];
__device__ __half g_bufQh[MAX_NODES * GNN_H];
__device__ float  g_bufS[MAX_NODES * GNN_H];
__device__ float  g_bufH[MAX_NODES * GNN_H];
__device__ int    g_deg[MAX_NODES];
__device__ int    g_cursor[MAX_NODES];
__device__ int    g_rowptr[MAX_NODES];
__device__ int    g_csr[MAX_EDGES];
__device__ float  g_gsum[NB * GNN_DIM];
__device__ int    g_gcnt[NB];

// ---------------------------------------------------------------------------
// Init / CSR build
// ---------------------------------------------------------------------------
__global__ void zero_kernel(int* deg, int* cursor, float* gsum, int* gcnt,
                            int n_nodes, int n_graphs)
{
    int i = blockIdx.x * blockDim.x + threadIdx.x;
    if (i < n_nodes) { deg[i] = 0; cursor[i] = 0; }
    if (i < n_graphs * GNN_DIM) gsum[i] = 0.f;
    if (i < n_graphs) gcnt[i] = 0;
}

__global__ void hist_kernel(const int* __restrict__ dst, int* __restrict__ deg, int n_edges)
{
    int e = blockIdx.x * blockDim.x + threadIdx.x;
    if (e < n_edges) atomicAdd(&deg[dst[e]], 1);
}

__global__ void count_kernel(const int* __restrict__ nb, int* __restrict__ gcnt, int n)
{
    int i = blockIdx.x * blockDim.x + threadIdx.x;
    if (i < n) atomicAdd(&gcnt[nb[i]], 1);
}

__global__ void scan_kernel(const int* __restrict__ deg, int* __restrict__ row_ptr, int n)
{
    __shared__ int part[1024];
    int t = threadIdx.x;
    int ch = (n + 1023) / 1024;
    int lo = t * ch;
    int hi = lo + ch; if (hi > n) hi = n;
    int s = 0;
    for (int i = lo; i < hi; i++) s += deg[i];
    part[t] = s;
    __syncthreads();
    for (int off = 1; off < 1024; off <<= 1) {
        int v = (t >= off) ? part[t - off] : 0;
        __syncthreads();
        part[t] += v;
        __syncthreads();
    }
    int run = (t == 0) ? 0 : part[t - 1];
    for (int i = lo; i < hi; i++) { row_ptr[i] = run; run += deg[i]; }
}

__global__ void fill_kernel(const int* __restrict__ src, const int* __restrict__ dst,
                            const int* __restrict__ row_ptr, int* __restrict__ cursor,
                            int* __restrict__ csr, int n_edges)
{
    int e = blockIdx.x * blockDim.x + threadIdx.x;
    if (e >= n_edges) return;
    int d = dst[e];
    int pos = atomicAdd(&cursor[d], 1);
    csr[row_ptr[d] + pos] = src[e];
}

// ---------------------------------------------------------------------------
// Tensor-core GEMM (3xTF32 split -> fp32 accuracy) C[M,N] = A[M,K] @ W[K,N]
// Block tile 128x64, 8 warps, each warp 32x32 via mma.sync.m16n8k8.tf32.
// flags: bias | relu | mask(deg==0 -> 0) | pool(atomic gsum, no C write)
//        | halfout(write fp16 to Ch)
// ---------------------------------------------------------------------------
#define FLAG_BIAS 1
#define FLAG_RELU 2
#define FLAG_MASK 4
#define FLAG_POOL 8
#define FLAG_HALF 16

__device__ __forceinline__ uint32_t f2tf32(float x)
{
    uint32_t r;
    asm("cvt.rna.tf32.f32 %0, %1;" : "=r"(r) : "f"(x));
    return r;
}

__device__ __forceinline__ void mma8(float c[4], const uint32_t a[4], const uint32_t b[2])
{
    asm volatile(
        "mma.sync.aligned.m16n8k8.row.col.f32.tf32.tf32.f32 "
        "{%0,%1,%2,%3}, {%4,%5,%6,%7}, {%8,%9}, {%0,%1,%2,%3};"
        : "+f"(c[0]), "+f"(c[1]), "+f"(c[2]), "+f"(c[3])
        : "r"(a[0]), "r"(a[1]), "r"(a[2]), "r"(a[3]), "r"(b[0]), "r"(b[1]));
}

__global__ __launch_bounds__(256) void gemm_tc(
    const float* __restrict__ A, const float* __restrict__ W,
    const float* __restrict__ bias, const int* __restrict__ deg,
    const int* __restrict__ nb,
    float* __restrict__ C, __half* __restrict__ Ch, float* __restrict__ gsum,
    int M, int N, int K, int lda, int ldw, int ldc, int flags)
{
    __shared__ float As[128][20];   // [m][k], pad 20 -> conflict-free frag loads
    __shared__ float Bs[16][72];    // [k][n], pad 72

    const int tid    = threadIdx.x;
    const int wid    = tid >> 5;
    const int lane   = tid & 31;
    const int g      = lane >> 2;   // 0..7
    const int ti     = lane & 3;    // 0..3
    const int warp_m = wid & 3;     // 0..3 -> 32-row slabs
    const int warp_n = wid >> 2;    // 0..1 -> 32-col slabs
    const int bm     = blockIdx.x * 128;
    const int bn     = blockIdx.y * 64;

    const int ar = tid >> 2;           // 0..63
    const int ac = (tid & 3) * 4;      // 0..12
    const int wr = tid >> 4;           // 0..15
    const int wc = (tid & 15) * 4;     // 0..60

    float acc[2][4][4] = {};

    for (int kt = 0; kt < K; kt += 16) {
        #pragma unroll
        for (int r = 0; r < 2; r++) {
            int row  = ar + r * 64;
            int grow = bm + row;
            float4 v = make_float4(0.f, 0.f, 0.f, 0.f);
            if (grow < M) v = *(const float4*)(A + (size_t)grow * lda + kt + ac);
            As[row][ac + 0] = v.x; As[row][ac + 1] = v.y;
            As[row][ac + 2] = v.z; As[row][ac + 3] = v.w;
        }
        {
            float4 v = *(const float4*)(W + (size_t)(kt + wr) * ldw + bn + wc);
            Bs[wr][wc + 0] = v.x; Bs[wr][wc + 1] = v.y;
            Bs[wr][wc + 2] = v.z; Bs[wr][wc + 3] = v.w;
        }
        __syncthreads();

        #pragma unroll
        for (int k0 = 0; k0 < 16; k0 += 8) {
            uint32_t ahi[2][4], alo[2][4];
            #pragma unroll
            for (int mt = 0; mt < 2; mt++) {
                int mrow = warp_m * 32 + mt * 16 + g;
                float av[4];
                av[0] = As[mrow][k0 + ti];
                av[1] = As[mrow + 8][k0 + ti];
                av[2] = As[mrow][k0 + ti + 4];
                av[3] = As[mrow + 8][k0 + ti + 4];
                #pragma unroll
                for (int i = 0; i < 4; i++) {
                    uint32_t h = f2tf32(av[i]);
                    ahi[mt][i] = h;
                    alo[mt][i] = f2tf32(av[i] - __uint_as_float(h));
                }
            }
            uint32_t bhi[4][2], blo[4][2];
            #pragma unroll
            for (int nt = 0; nt < 4; nt++) {
                int ncol = warp_n * 32 + nt * 8 + g;
                float bv[2];
                bv[0] = Bs[k0 + ti][ncol];
                bv[1] = Bs[k0 + ti + 4][ncol];
                #pragma unroll
                for (int i = 0; i < 2; i++) {
                    uint32_t h = f2tf32(bv[i]);
                    bhi[nt][i] = h;
                    blo[nt][i] = f2tf32(bv[i] - __uint_as_float(h));
                }
            }
            #pragma unroll
            for (int mt = 0; mt < 2; mt++)
                #pragma unroll
                for (int nt = 0; nt < 4; nt++) {
                    mma8(acc[mt][nt], ahi[mt], bhi[nt]);
                    mma8(acc[mt][nt], ahi[mt], blo[nt]);
                    mma8(acc[mt][nt], alo[mt], bhi[nt]);
                }
        }
        __syncthreads();
    }

    // epilogue
    #pragma unroll
    for (int mt = 0; mt < 2; mt++) {
        #pragma unroll
        for (int i = 0; i < 2; i++) {
            int row = bm + warp_m * 32 + mt * 16 + g + i * 8;
            if (row >= M) continue;
            bool zero = (flags & FLAG_MASK) && (deg[row] == 0);
            int batch = (flags & FLAG_POOL) ? nb[row] : 0;
            #pragma unroll
            for (int nt = 0; nt < 4; nt++) {
                int col = bn + warp_n * 32 + nt * 8 + ti * 2;
                float v0 = acc[mt][nt][i * 2 + 0];
                float v1 = acc[mt][nt][i * 2 + 1];
                if (flags & FLAG_BIAS) { v0 += bias[col]; v1 += bias[col + 1]; }
                if (flags & FLAG_RELU) { v0 = fmaxf(v0, 0.f); v1 = fmaxf(v1, 0.f); }
                if (zero) { v0 = 0.f; v1 = 0.f; }
                if (flags & FLAG_POOL) {
                    atomicAdd(&gsum[batch * GNN_DIM + col],     v0);
                    atomicAdd(&gsum[batch * GNN_DIM + col + 1], v1);
                } else if (flags & FLAG_HALF) {
                    *(__half2*)(Ch + (size_t)row * ldc + col) = __floats2half2_rn(v0, v1);
                } else {
                    *(float2*)(C + (size_t)row * ldc + col) = make_float2(v0, v1);
                }
            }
        }
    }
}

// ---------------------------------------------------------------------------
// Edge gather-reduce with fp16 Q: S[n] = mean_{e: dst=n} relu(P[n] + Q[src_e])
// LANES threads per node; each lane owns 8 features (16B fp16 per edge load).
// ---------------------------------------------------------------------------
template <int LANES>
__global__ void gather_half_kernel(
    const float* __restrict__ P, const __half* __restrict__ Q,
    const int* __restrict__ row_ptr, const int* __restrict__ deg,
    const int* __restrict__ csr, float* __restrict__ S, int n_nodes)
{
    const int FEAT = LANES * 8;
    int gid  = blockIdx.x * blockDim.x + threadIdx.x;
    int node = gid / LANES;
    int sub  = gid % LANES;
    if (node >= n_nodes) return;

    const float4* pp = (const float4*)(P + (size_t)node * FEAT + sub * 8);
    float4 p0 = pp[0], p1 = pp[1];
    float acc[8] = {0.f, 0.f, 0.f, 0.f, 0.f, 0.f, 0.f, 0.f};

    int start = row_ptr[node];
    int d     = deg[node];
    int s_next = (d > 0) ? csr[start] : 0;

    for (int i = 0; i < d; i++) {
        int s = s_next;
        if (i + 1 < d) s_next = csr[start + i + 1];
        uint4 qv = *(const uint4*)(Q + (size_t)s * FEAT + sub * 8);
        float2 f0 = __half22float2(*(__half2*)&qv.x);
        float2 f1 = __half22float2(*(__half2*)&qv.y);
        float2 f2 = __half22float2(*(__half2*)&qv.z);
        float2 f3 = __half22float2(*(__half2*)&qv.w);
        acc[0] += fmaxf(p0.x + f0.x, 0.f);
        acc[1] += fmaxf(p0.y + f0.y, 0.f);
        acc[2] += fmaxf(p0.z + f1.x, 0.f);
        acc[3] += fmaxf(p0.w + f1.y, 0.f);
        acc[4] += fmaxf(p1.x + f2.x, 0.f);
        acc[5] += fmaxf(p1.y + f2.y, 0.f);
        acc[6] += fmaxf(p1.z + f3.x, 0.f);
        acc[7] += fmaxf(p1.w + f3.y, 0.f);
    }
    float inv = 1.0f / (float)(d > 0 ? d : 1);
    float4 o0 = make_float4(acc[0] * inv, acc[1] * inv, acc[2] * inv, acc[3] * inv);
    float4 o1 = make_float4(acc[4] * inv, acc[5] * inv, acc[6] * inv, acc[7] * inv);
    float4* sp = (float4*)(S + (size_t)node * FEAT + sub * 8);
    sp[0] = o0;
    sp[1] = o1;
}

// ---------------------------------------------------------------------------
// Actor head (one block per graph)
// ---------------------------------------------------------------------------
__global__ __launch_bounds__(256) void head_kernel(
    const float* __restrict__ state,
    const float* __restrict__ gsum, const int* __restrict__ gcnt,
    const float* __restrict__ fc1_w, const float* __restrict__ fc1_b,
    const float* __restrict__ fc2_w, const float* __restrict__ fc2_b,
    const float* __restrict__ mean_w, const float* __restrict__ mean_b,
    const float* __restrict__ ls_w, const float* __restrict__ ls_b,
    float* __restrict__ out, int n_graphs)
{
    __shared__ float z[128];
    __shared__ float h1[256];
    __shared__ float h2[256];
    int b = blockIdx.x;
    int t = threadIdx.x;
    if (b >= n_graphs) return;

    if (t < 64) {
        z[t] = state[b * 64 + t];
    } else if (t < 128) {
        float c = fmaxf((float)gcnt[b], 1.f);
        z[t] = gsum[b * GNN_DIM + (t - 64)] / c;
    }
    __syncthreads();

    {
        float s = fc1_b[t];
        #pragma unroll 4
        for (int k = 0; k < 128; k++) s += z[k] * fc1_w[k * 256 + t];
        h1[t] = fmaxf(s, 0.f);
    }
    __syncthreads();
    {
        float s = fc2_b[t];
        #pragma unroll 4
        for (int k = 0; k < 256; k++) s += h1[k] * fc2_w[k * 256 + t];
        h2[t] = fmaxf(s, 0.f);
    }
    __syncthreads();

    if (t < ACTION_DIM) {
        float s = mean_b[t];
        #pragma unroll 4
        for (int k = 0; k < 256; k++) s += h2[k] * mean_w[k * ACTION_DIM + t];
        out[b * ACTION_DIM + t] = s;
    } else if (t < 2 * ACTION_DIM) {
        int j = t - ACTION_DIM;
        float s = ls_b[j];
        #pragma unroll 4
        for (int k = 0; k < 256; k++) s += h2[k] * ls_w[k * ACTION_DIM + j];
        s = fminf(fmaxf(s, -20.f), 2.f);
        out[n_graphs * ACTION_DIM + b * ACTION_DIM + j] = s;
    }
}

// ---------------------------------------------------------------------------
// Launch
// ---------------------------------------------------------------------------
extern "C" void kernel_launch(void* const* d_in, const int* in_sizes, int n_in,
                              void* d_out, int out_size)
{
    const float* state  = (const float*)d_in[0];
    const float* x      = (const float*)d_in[1];
    const int*   eidx   = (const int*)  d_in[2];
    const int*   nbatch = (const int*)  d_in[3];
    const float* g1w1   = (const float*)d_in[4];
    const float* g1b1   = (const float*)d_in[5];
    const float* g1w2   = (const float*)d_in[6];
    const float* g1b2   = (const float*)d_in[7];
    const float* g2w1   = (const float*)d_in[8];
    const float* g2b1   = (const float*)d_in[9];
    const float* g2w2   = (const float*)d_in[10];
    const float* g2b2   = (const float*)d_in[11];
    const float* fc1_w  = (const float*)d_in[12];
    const float* fc1_b  = (const float*)d_in[13];
    const float* fc2_w  = (const float*)d_in[14];
    const float* fc2_b  = (const float*)d_in[15];
    const float* mean_w = (const float*)d_in[16];
    const float* mean_b = (const float*)d_in[17];
    const float* ls_w   = (const float*)d_in[18];
    const float* ls_b   = (const float*)d_in[19];
    float* out = (float*)d_out;

    const int n_graphs = in_sizes[0] / 64;
    const int n_nodes  = in_sizes[1] / NODE_DIM;
    const int n_edges  = in_sizes[2] / 2;
    const int* e_src = eidx;
    const int* e_dst = eidx + n_edges;

    float *bufP, *bufS, *bufH, *gsum;
    __half *bufQh;
    int *deg, *cursor, *rowptr, *csr, *gcnt;
    cudaGetSymbolAddress((void**)&bufP,   g_bufP);
    cudaGetSymbolAddress((void**)&bufQh,  g_bufQh);
    cudaGetSymbolAddress((void**)&bufS,   g_bufS);
    cudaGetSymbolAddress((void**)&bufH,   g_bufH);
    cudaGetSymbolAddress((void**)&deg,    g_deg);
    cudaGetSymbolAddress((void**)&cursor, g_cursor);
    cudaGetSymbolAddress((void**)&rowptr, g_rowptr);
    cudaGetSymbolAddress((void**)&csr,    g_csr);
    cudaGetSymbolAddress((void**)&gsum,   g_gsum);
    cudaGetSymbolAddress((void**)&gcnt,   g_gcnt);

    // init + CSR build
    zero_kernel<<<(n_nodes + 255) / 256, 256>>>(deg, cursor, gsum, gcnt, n_nodes, n_graphs);
    int eblocks = (n_edges + 255) / 256;
    hist_kernel<<<eblocks, 256>>>(e_dst, deg, n_edges);
    count_kernel<<<(n_nodes + 255) / 256, 256>>>(nbatch, gcnt, n_nodes);
    scan_kernel<<<1, 1024>>>(deg, rowptr, n_nodes);
    fill_kernel<<<eblocks, 256>>>(e_src, e_dst, rowptr, cursor, csr, n_edges);

    const int mb = (n_nodes + 127) / 128;
    dim3 blk(256);

    // ---- GNN layer 1 ----
    // P1 = x @ W1[:64,:] + b1     [N,128] fp32
    gemm_tc<<<dim3(mb, 2), blk>>>(x, g1w1, g1b1, deg, nbatch,
                                  bufP, nullptr, gsum,
                                  n_nodes, 128, 64, 64, 128, 128, FLAG_BIAS);
    // Q1 = x @ W1[64:,:]          [N,128] fp16
    gemm_tc<<<dim3(mb, 2), blk>>>(x, g1w1 + 64 * 128, nullptr, deg, nbatch,
                                  nullptr, bufQh, gsum,
                                  n_nodes, 128, 64, 64, 128, 128, FLAG_HALF);
    // S1 = mean_dst relu(P1[dst] + Q1[src])
    {
        int total = n_nodes * 16;
        gather_half_kernel<16><<<(total + 255) / 256, 256>>>(bufP, bufQh, rowptr, deg, csr, bufS, n_nodes);
    }
    // H1 = relu(mask(S1 @ W2 + b2))   [N,128]
    gemm_tc<<<dim3(mb, 2), blk>>>(bufS, g1w2, g1b2, deg, nbatch,
                                  bufH, nullptr, gsum,
                                  n_nodes, 128, 128, 128, 128, 128,
                                  FLAG_BIAS | FLAG_RELU | FLAG_MASK);

    // ---- GNN layer 2 ----
    // P2 = H1 @ W1[:128,:] + b1   [N,64] fp32
    gemm_tc<<<dim3(mb, 1), blk>>>(bufH, g2w1, g2b1, deg, nbatch,
                                  bufP, nullptr, gsum,
                                  n_nodes, 64, 128, 128, 64, 64, FLAG_BIAS);
    // Q2 = H1 @ W1[128:,:]        [N,64] fp16
    gemm_tc<<<dim3(mb, 1), blk>>>(bufH, g2w1 + 128 * 64, nullptr, deg, nbatch,
                                  nullptr, bufQh, gsum,
                                  n_nodes, 64, 128, 128, 64, 64, FLAG_HALF);
    // S2
    {
        int total = n_nodes * 8;
        gather_half_kernel<8><<<(total + 255) / 256, 256>>>(bufP, bufQh, rowptr, deg, csr, bufS, n_nodes);
    }
    // H2 = mask(S2 @ W2 + b2) pooled directly into gsum (no C write)
    gemm_tc<<<dim3(mb, 1), blk>>>(bufS, g2w2, g2b2, deg, nbatch,
                                  nullptr, nullptr, gsum,
                                  n_nodes, 64, 64, 64, 64, 64,
                                  FLAG_BIAS | FLAG_MASK | FLAG_POOL);

    // ---- head ----
    head_kernel<<<n_graphs, 256>>>(state, gsum, gcnt,
                                   fc1_w, fc1_b, fc2_w, fc2_b,
                                   mean_w, mean_b, ls_w, ls_b,
                                   out, n_graphs);
}

// round 3
// speedup vs baseline: 1.3604x; 1.1281x over previous
#include <cuda_runtime.h>
#include <cuda_fp16.h>
#include <cstdint>

// ---------------------------------------------------------------------------
// Problem constants
// ---------------------------------------------------------------------------
#define MAX_NODES 50000
#define MAX_EDGES 800000
#define NODE_DIM  64
#define GNN_H     128
#define GNN_DIM   64
#define NB        128
#define HIDDEN    256
#define ACTION_DIM 8
#define SCAN_BLK  1024

// ---------------------------------------------------------------------------
// Device scratch
// ---------------------------------------------------------------------------
__device__ __half g_bufPh[MAX_NODES * GNN_H];
__device__ __half g_bufQh[MAX_NODES * GNN_H];
__device__ float  g_bufS[MAX_NODES * GNN_H];
__device__ float  g_bufH[MAX_NODES * GNN_H];
__device__ int    g_deg[MAX_NODES];
__device__ int    g_cursor[MAX_NODES];
__device__ int    g_rowptr[MAX_NODES];
__device__ int    g_csr[MAX_EDGES];
__device__ int    g_bsum[(MAX_NODES + SCAN_BLK - 1) / SCAN_BLK];
__device__ float  g_gsum[NB * GNN_DIM];
__device__ int    g_gcnt[NB];

// ---------------------------------------------------------------------------
// Init + histogram (fused) 
// ---------------------------------------------------------------------------
__global__ void zero_kernel(int* deg, int* cursor, float* gsum, int* gcnt,
                            int n_nodes, int n_graphs)
{
    int i = blockIdx.x * blockDim.x + threadIdx.x;
    if (i < n_nodes) { deg[i] = 0; cursor[i] = 0; }
    if (i < n_graphs * GNN_DIM) gsum[i] = 0.f;
    if (i < n_graphs) gcnt[i] = 0;
}

__global__ void hist_count_kernel(const int* __restrict__ dst, int* __restrict__ deg,
                                  const int* __restrict__ nb, int* __restrict__ gcnt,
                                  int n_edges, int n_nodes)
{
    int i = blockIdx.x * blockDim.x + threadIdx.x;
    if (i < n_edges) atomicAdd(&deg[dst[i]], 1);
    if (i < n_nodes) atomicAdd(&gcnt[nb[i]], 1);
}

// ---------------------------------------------------------------------------
// Parallel scan: per-block smem scan + serial block-offset fixup
// ---------------------------------------------------------------------------
__global__ __launch_bounds__(SCAN_BLK) void scan_block_kernel(
    const int* __restrict__ deg, int* __restrict__ rowptr,
    int* __restrict__ bsum, int n)
{
    __shared__ int sm[SCAN_BLK];
    int t = threadIdx.x;
    int i = blockIdx.x * SCAN_BLK + t;
    int v = (i < n) ? deg[i] : 0;
    sm[t] = v;
    __syncthreads();
    #pragma unroll
    for (int off = 1; off < SCAN_BLK; off <<= 1) {
        int u = (t >= off) ? sm[t - off] : 0;
        __syncthreads();
        sm[t] += u;
        __syncthreads();
    }
    if (i < n) rowptr[i] = sm[t] - v;   // exclusive
    if (t == SCAN_BLK - 1) bsum[blockIdx.x] = sm[t];
}

__global__ __launch_bounds__(SCAN_BLK) void scan_fix_kernel(
    const int* __restrict__ bsum, int* __restrict__ rowptr, int n)
{
    __shared__ int s_off;
    int b = blockIdx.x;
    if (threadIdx.x == 0) {
        int s = 0;
        for (int j = 0; j < b; j++) s += bsum[j];
        s_off = s;
    }
    __syncthreads();
    int i = b * SCAN_BLK + threadIdx.x;
    if (i < n) rowptr[i] += s_off;
}

__global__ void fill_kernel(const int* __restrict__ src, const int* __restrict__ dst,
                            const int* __restrict__ row_ptr, int* __restrict__ cursor,
                            int* __restrict__ csr, int n_edges)
{
    int e = blockIdx.x * blockDim.x + threadIdx.x;
    if (e >= n_edges) return;
    int d = dst[e];
    int pos = atomicAdd(&cursor[d], 1);
    csr[row_ptr[d] + pos] = src[e];
}

// ---------------------------------------------------------------------------
// Tensor-core machinery (3xTF32 split -> fp32 accuracy)
// ---------------------------------------------------------------------------
__device__ __forceinline__ uint32_t f2tf32(float x)
{
    uint32_t r;
    asm("cvt.rna.tf32.f32 %0, %1;" : "=r"(r) : "f"(x));
    return r;
}

__device__ __forceinline__ void mma8(float c[4], const uint32_t a[4], const uint32_t b[2])
{
    asm volatile(
        "mma.sync.aligned.m16n8k8.row.col.f32.tf32.tf32.f32 "
        "{%0,%1,%2,%3}, {%4,%5,%6,%7}, {%8,%9}, {%0,%1,%2,%3};"
        : "+f"(c[0]), "+f"(c[1]), "+f"(c[2]), "+f"(c[3])
        : "r"(a[0]), "r"(a[1]), "r"(a[2]), "r"(a[3]), "r"(b[0]), "r"(b[1]));
}

// Core MMA loop shared by both GEMM kernels. Block tile 128x64, 8 warps.
struct MmaCtx {
    int tid, wid, lane, g, ti, warp_m, warp_n;
};

__device__ __forceinline__ void gemm_core(
    const float* __restrict__ A, const float* __restrict__ W,
    int M, int K, int lda, int ldw, int bm, int bn,
    float (&As)[128][20], float (&Bs)[16][72],
    const MmaCtx& c, float acc[2][4][4])
{
    const int ar = c.tid >> 2;
    const int ac = (c.tid & 3) * 4;
    const int wr = c.tid >> 4;
    const int wc = (c.tid & 15) * 4;

    for (int kt = 0; kt < K; kt += 16) {
        #pragma unroll
        for (int r = 0; r < 2; r++) {
            int row  = ar + r * 64;
            int grow = bm + row;
            float4 v = make_float4(0.f, 0.f, 0.f, 0.f);
            if (grow < M) v = *(const float4*)(A + (size_t)grow * lda + kt + ac);
            As[row][ac + 0] = v.x; As[row][ac + 1] = v.y;
            As[row][ac + 2] = v.z; As[row][ac + 3] = v.w;
        }
        {
            float4 v = *(const float4*)(W + (size_t)(kt + wr) * ldw + bn + wc);
            Bs[wr][wc + 0] = v.x; Bs[wr][wc + 1] = v.y;
            Bs[wr][wc + 2] = v.z; Bs[wr][wc + 3] = v.w;
        }
        __syncthreads();

        #pragma unroll
        for (int k0 = 0; k0 < 16; k0 += 8) {
            uint32_t ahi[2][4], alo[2][4];
            #pragma unroll
            for (int mt = 0; mt < 2; mt++) {
                int mrow = c.warp_m * 32 + mt * 16 + c.g;
                float av[4];
                av[0] = As[mrow][k0 + c.ti];
                av[1] = As[mrow + 8][k0 + c.ti];
                av[2] = As[mrow][k0 + c.ti + 4];
                av[3] = As[mrow + 8][k0 + c.ti + 4];
                #pragma unroll
                for (int i = 0; i < 4; i++) {
                    uint32_t h = f2tf32(av[i]);
                    ahi[mt][i] = h;
                    alo[mt][i] = f2tf32(av[i] - __uint_as_float(h));
                }
            }
            uint32_t bhi[4][2], blo[4][2];
            #pragma unroll
            for (int nt = 0; nt < 4; nt++) {
                int ncol = c.warp_n * 32 + nt * 8 + c.g;
                float bv[2];
                bv[0] = Bs[k0 + c.ti][ncol];
                bv[1] = Bs[k0 + c.ti + 4][ncol];
                #pragma unroll
                for (int i = 0; i < 2; i++) {
                    uint32_t h = f2tf32(bv[i]);
                    bhi[nt][i] = h;
                    blo[nt][i] = f2tf32(bv[i] - __uint_as_float(h));
                }
            }
            #pragma unroll
            for (int mt = 0; mt < 2; mt++)
                #pragma unroll
                for (int nt = 0; nt < 4; nt++) {
                    mma8(acc[mt][nt], ahi[mt], bhi[nt]);
                    mma8(acc[mt][nt], ahi[mt], blo[nt]);
                    mma8(acc[mt][nt], alo[mt], bhi[nt]);
                }
        }
        __syncthreads();
    }
}

__device__ __forceinline__ MmaCtx make_ctx()
{
    MmaCtx c;
    c.tid = threadIdx.x;
    c.wid = c.tid >> 5;
    c.lane = c.tid & 31;
    c.g = c.lane >> 2;
    c.ti = c.lane & 3;
    c.warp_m = c.wid & 3;
    c.warp_n = c.wid >> 2;
    return c;
}

// ---------------------------------------------------------------------------
// Fused P/Q GEMM: blockIdx.y selects W-half; both outputs fp16.
// P half (first ntile_y tiles): bias added.  Q half: no bias.
// ---------------------------------------------------------------------------
__global__ __launch_bounds__(256) void gemm_pq(
    const float* __restrict__ A,
    const float* __restrict__ Wp, const float* __restrict__ Wq,
    const float* __restrict__ biasp,
    __half* __restrict__ Ph, __half* __restrict__ Qh,
    int M, int N, int K, int lda, int ldw)
{
    __shared__ float As[128][20];
    __shared__ float Bs[16][72];

    MmaCtx c = make_ctx();
    const int ntile = N >> 6;                 // 64-col tiles per half
    const int is_q  = (blockIdx.y >= (unsigned)ntile);
    const int bn    = (blockIdx.y - (is_q ? ntile : 0)) * 64;
    const int bm    = blockIdx.x * 128;
    const float* W  = is_q ? Wq : Wp;
    __half* out     = is_q ? Qh : Ph;

    float acc[2][4][4] = {};
    gemm_core(A, W, M, K, lda, ldw, bm, bn, As, Bs, c, acc);

    #pragma unroll
    for (int mt = 0; mt < 2; mt++) {
        #pragma unroll
        for (int i = 0; i < 2; i++) {
            int row = bm + c.warp_m * 32 + mt * 16 + c.g + i * 8;
            if (row >= M) continue;
            #pragma unroll
            for (int nt = 0; nt < 4; nt++) {
                int col = bn + c.warp_n * 32 + nt * 8 + c.ti * 2;
                float v0 = acc[mt][nt][i * 2 + 0];
                float v1 = acc[mt][nt][i * 2 + 1];
                if (!is_q) { v0 += biasp[col]; v1 += biasp[col + 1]; }
                *(__half2*)(out + (size_t)row * N + col) = __floats2half2_rn(v0, v1);
            }
        }
    }
}

// ---------------------------------------------------------------------------
// GEMM with fp32/pool epilogue (H1 and H2-pool)
// ---------------------------------------------------------------------------
#define FLAG_BIAS 1
#define FLAG_RELU 2
#define FLAG_MASK 4
#define FLAG_POOL 8

__global__ __launch_bounds__(256) void gemm_tc(
    const float* __restrict__ A, const float* __restrict__ W,
    const float* __restrict__ bias, const int* __restrict__ deg,
    const int* __restrict__ nb,
    float* __restrict__ C, float* __restrict__ gsum,
    int M, int N, int K, int lda, int ldw, int ldc, int flags)
{
    __shared__ float As[128][20];
    __shared__ float Bs[16][72];

    MmaCtx c = make_ctx();
    const int bm = blockIdx.x * 128;
    const int bn = blockIdx.y * 64;

    float acc[2][4][4] = {};
    gemm_core(A, W, M, K, lda, ldw, bm, bn, As, Bs, c, acc);

    #pragma unroll
    for (int mt = 0; mt < 2; mt++) {
        #pragma unroll
        for (int i = 0; i < 2; i++) {
            int row = bm + c.warp_m * 32 + mt * 16 + c.g + i * 8;
            if (row >= M) continue;
            bool zero = (flags & FLAG_MASK) && (deg[row] == 0);
            int batch = (flags & FLAG_POOL) ? nb[row] : 0;
            #pragma unroll
            for (int nt = 0; nt < 4; nt++) {
                int col = bn + c.warp_n * 32 + nt * 8 + c.ti * 2;
                float v0 = acc[mt][nt][i * 2 + 0];
                float v1 = acc[mt][nt][i * 2 + 1];
                if (flags & FLAG_BIAS) { v0 += bias[col]; v1 += bias[col + 1]; }
                if (flags & FLAG_RELU) { v0 = fmaxf(v0, 0.f); v1 = fmaxf(v1, 0.f); }
                if (zero) { v0 = 0.f; v1 = 0.f; }
                if (flags & FLAG_POOL) {
                    atomicAdd(&gsum[batch * GNN_DIM + col],     v0);
                    atomicAdd(&gsum[batch * GNN_DIM + col + 1], v1);
                } else {
                    *(float2*)(C + (size_t)row * ldc + col) = make_float2(v0, v1);
                }
            }
        }
    }
}

// ---------------------------------------------------------------------------
// Edge gather-reduce, all-half2 math with half2 accumulators.
// S[n] = mean_{e: dst=n} relu(P[n] + Q[src_e]); S written fp32.
// LANES lanes per node; each lane owns 8 features (one uint4 of fp16).
// ---------------------------------------------------------------------------
template <int LANES>
__global__ void gather_h2_kernel(
    const __half* __restrict__ P, const __half* __restrict__ Q,
    const int* __restrict__ row_ptr, const int* __restrict__ deg,
    const int* __restrict__ csr, float* __restrict__ S, int n_nodes)
{
    const int FEAT = LANES * 8;
    int gid  = blockIdx.x * blockDim.x + threadIdx.x;
    int node = gid / LANES;
    int sub  = gid % LANES;
    if (node >= n_nodes) return;

    uint4 pv = *(const uint4*)(P + (size_t)node * FEAT + sub * 8);
    __half2 p0 = *(__half2*)&pv.x, p1 = *(__half2*)&pv.y;
    __half2 p2 = *(__half2*)&pv.z, p3 = *(__half2*)&pv.w;

    const __half2 z2 = __float2half2_rn(0.f);
    __half2 a0 = z2, a1 = z2, a2 = z2, a3 = z2;

    int start = row_ptr[node];
    int d     = deg[node];

    if (d > 0) {
        int s = csr[start];
        uint4 qv = *(const uint4*)(Q + (size_t)s * FEAT + sub * 8);
        for (int i = 0; i < d; i++) {
            // prefetch next edge
            uint4 qn = qv;
            if (i + 1 < d) {
                int sn = csr[start + i + 1];
                qn = *(const uint4*)(Q + (size_t)sn * FEAT + sub * 8);
            }
            a0 = __hadd2(a0, __hmax2(__hadd2(p0, *(__half2*)&qv.x), z2));
            a1 = __hadd2(a1, __hmax2(__hadd2(p1, *(__half2*)&qv.y), z2));
            a2 = __hadd2(a2, __hmax2(__hadd2(p2, *(__half2*)&qv.z), z2));
            a3 = __hadd2(a3, __hmax2(__hadd2(p3, *(__half2*)&qv.w), z2));
            qv = qn;
        }
    }

    float inv = 1.0f / (float)(d > 0 ? d : 1);
    float2 f0 = __half22float2(a0), f1 = __half22float2(a1);
    float2 f2 = __half22float2(a2), f3 = __half22float2(a3);
    float4* sp = (float4*)(S + (size_t)node * FEAT + sub * 8);
    sp[0] = make_float4(f0.x * inv, f0.y * inv, f1.x * inv, f1.y * inv);
    sp[1] = make_float4(f2.x * inv, f2.y * inv, f3.x * inv, f3.y * inv);
}

// ---------------------------------------------------------------------------
// Actor head (one block per graph)
// ---------------------------------------------------------------------------
__global__ __launch_bounds__(256) void head_kernel(
    const float* __restrict__ state,
    const float* __restrict__ gsum, const int* __restrict__ gcnt,
    const float* __restrict__ fc1_w, const float* __restrict__ fc1_b,
    const float* __restrict__ fc2_w, const float* __restrict__ fc2_b,
    const float* __restrict__ mean_w, const float* __restrict__ mean_b,
    const float* __restrict__ ls_w, const float* __restrict__ ls_b,
    float* __restrict__ out, int n_graphs)
{
    __shared__ float z[128];
    __shared__ float h1[256];
    __shared__ float h2[256];
    int b = blockIdx.x;
    int t = threadIdx.x;
    if (b >= n_graphs) return;

    if (t < 64) {
        z[t] = state[b * 64 + t];
    } else if (t < 128) {
        float c = fmaxf((float)gcnt[b], 1.f);
        z[t] = gsum[b * GNN_DIM + (t - 64)] / c;
    }
    __syncthreads();

    {
        float s = fc1_b[t];
        #pragma unroll 4
        for (int k = 0; k < 128; k++) s += z[k] * fc1_w[k * 256 + t];
        h1[t] = fmaxf(s, 0.f);
    }
    __syncthreads();
    {
        float s = fc2_b[t];
        #pragma unroll 4
        for (int k = 0; k < 256; k++) s += h1[k] * fc2_w[k * 256 + t];
        h2[t] = fmaxf(s, 0.f);
    }
    __syncthreads();

    if (t < ACTION_DIM) {
        float s = mean_b[t];
        #pragma unroll 4
        for (int k = 0; k < 256; k++) s += h2[k] * mean_w[k * ACTION_DIM + t];
        out[b * ACTION_DIM + t] = s;
    } else if (t < 2 * ACTION_DIM) {
        int j = t - ACTION_DIM;
        float s = ls_b[j];
        #pragma unroll 4
        for (int k = 0; k < 256; k++) s += h2[k] * ls_w[k * ACTION_DIM + j];
        s = fminf(fmaxf(s, -20.f), 2.f);
        out[n_graphs * ACTION_DIM + b * ACTION_DIM + j] = s;
    }
}

// ---------------------------------------------------------------------------
// Launch
// ---------------------------------------------------------------------------
extern "C" void kernel_launch(void* const* d_in, const int* in_sizes, int n_in,
                              void* d_out, int out_size)
{
    const float* state  = (const float*)d_in[0];
    const float* x      = (const float*)d_in[1];
    const int*   eidx   = (const int*)  d_in[2];
    const int*   nbatch = (const int*)  d_in[3];
    const float* g1w1   = (const float*)d_in[4];
    const float* g1b1   = (const float*)d_in[5];
    const float* g1w2   = (const float*)d_in[6];
    const float* g1b2   = (const float*)d_in[7];
    const float* g2w1   = (const float*)d_in[8];
    const float* g2b1   = (const float*)d_in[9];
    const float* g2w2   = (const float*)d_in[10];
    const float* g2b2   = (const float*)d_in[11];
    const float* fc1_w  = (const float*)d_in[12];
    const float* fc1_b  = (const float*)d_in[13];
    const float* fc2_w  = (const float*)d_in[14];
    const float* fc2_b  = (const float*)d_in[15];
    const float* mean_w = (const float*)d_in[16];
    const float* mean_b = (const float*)d_in[17];
    const float* ls_w   = (const float*)d_in[18];
    const float* ls_b   = (const float*)d_in[19];
    float* out = (float*)d_out;

    const int n_graphs = in_sizes[0] / 64;
    const int n_nodes  = in_sizes[1] / NODE_DIM;
    const int n_edges  = in_sizes[2] / 2;
    const int* e_src = eidx;
    const int* e_dst = eidx + n_edges;

    float *bufS, *bufH, *gsum;
    __half *bufPh, *bufQh;
    int *deg, *cursor, *rowptr, *csr, *gcnt, *bsum;
    cudaGetSymbolAddress((void**)&bufPh,  g_bufPh);
    cudaGetSymbolAddress((void**)&bufQh,  g_bufQh);
    cudaGetSymbolAddress((void**)&bufS,   g_bufS);
    cudaGetSymbolAddress((void**)&bufH,   g_bufH);
    cudaGetSymbolAddress((void**)&deg,    g_deg);
    cudaGetSymbolAddress((void**)&cursor, g_cursor);
    cudaGetSymbolAddress((void**)&rowptr, g_rowptr);
    cudaGetSymbolAddress((void**)&csr,    g_csr);
    cudaGetSymbolAddress((void**)&bsum,   g_bsum);
    cudaGetSymbolAddress((void**)&gsum,   g_gsum);
    cudaGetSymbolAddress((void**)&gcnt,   g_gcnt);

    // init + CSR build
    zero_kernel<<<(n_nodes + 255) / 256, 256>>>(deg, cursor, gsum, gcnt, n_nodes, n_graphs);
    int eblocks = (n_edges + 255) / 256;
    hist_count_kernel<<<eblocks, 256>>>(e_dst, deg, nbatch, gcnt, n_edges, n_nodes);
    int sblocks = (n_nodes + SCAN_BLK - 1) / SCAN_BLK;
    scan_block_kernel<<<sblocks, SCAN_BLK>>>(deg, rowptr, bsum, n_nodes);
    scan_fix_kernel<<<sblocks, SCAN_BLK>>>(bsum, rowptr, n_nodes);
    fill_kernel<<<eblocks, 256>>>(e_src, e_dst, rowptr, cursor, csr, n_edges);

    const int mb = (n_nodes + 127) / 128;

    // ---- GNN layer 1 ----
    // P1 = x@W1[:64,:] + b1 (fp16) ; Q1 = x@W1[64:,:] (fp16), one launch
    gemm_pq<<<dim3(mb, 4), 256>>>(x, g1w1, g1w1 + 64 * 128, g1b1,
                                  bufPh, bufQh,
                                  n_nodes, 128, 64, 64, 128);
    // S1 = mean_dst relu(P1[dst] + Q1[src])
    gather_h2_kernel<16><<<(n_nodes * 16 + 255) / 256, 256>>>(
        bufPh, bufQh, rowptr, deg, csr, bufS, n_nodes);
    // H1 = relu(mask(S1 @ W2 + b2))   [N,128] fp32
    gemm_tc<<<dim3(mb, 2), 256>>>(bufS, g1w2, g1b2, deg, nbatch,
                                  bufH, gsum,
                                  n_nodes, 128, 128, 128, 128, 128,
                                  FLAG_BIAS | FLAG_RELU | FLAG_MASK);

    // ---- GNN layer 2 ----
    gemm_pq<<<dim3(mb, 2), 256>>>(bufH, g2w1, g2w1 + 128 * 64, g2b1,
                                  bufPh, bufQh,
                                  n_nodes, 64, 128, 128, 64);
    gather_h2_kernel<8><<<(n_nodes * 8 + 255) / 256, 256>>>(
        bufPh, bufQh, rowptr, deg, csr, bufS, n_nodes);
    // H2 = mask(S2 @ W2 + b2) pooled directly into gsum
    gemm_tc<<<dim3(mb, 1), 256>>>(bufS, g2w2, g2b2, deg, nbatch,
                                  nullptr, gsum,
                                  n_nodes, 64, 64, 64, 64, 64,
                                  FLAG_BIAS | FLAG_MASK | FLAG_POOL);

    // ---- head ----
    head_kernel<<<n_graphs, 256>>>(state, gsum, gcnt,
                                   fc1_w, fc1_b, fc2_w, fc2_b,
                                   mean_w, mean_b, ls_w, ls_b,
                                   out, n_graphs);
}

// round 4
// speedup vs baseline: 1.6416x; 1.2067x over previous
#include <cuda_runtime.h>
#include <cuda_fp16.h>
#include <cstdint>

// ---------------------------------------------------------------------------
// Problem constants
// ---------------------------------------------------------------------------
#define MAX_NODES 50000
#define MAX_EDGES 800000
#define NODE_DIM  64
#define GNN_H     128
#define GNN_DIM   64
#define NB        128
#define HIDDEN    256
#define ACTION_DIM 8
#define SCAN_BLK  1024

// ---------------------------------------------------------------------------
// Device scratch (all intermediates fp16)
// ---------------------------------------------------------------------------
__device__ __half g_bufXh[MAX_NODES * NODE_DIM];
__device__ __half g_bufPh[MAX_NODES * GNN_H];
__device__ __half g_bufQh[MAX_NODES * GNN_H];
__device__ __half g_bufSh[MAX_NODES * GNN_H];
__device__ __half g_bufHh[MAX_NODES * GNN_H];
__device__ int    g_deg[MAX_NODES];
__device__ int    g_cursor[MAX_NODES];
__device__ int    g_rowptr[MAX_NODES];
__device__ int    g_csr[MAX_EDGES];
__device__ int    g_bsum[(MAX_NODES + SCAN_BLK - 1) / SCAN_BLK];
__device__ float  g_gsum[NB * GNN_DIM];
__device__ int    g_gcnt[NB];

// ---------------------------------------------------------------------------
// Init + histogram
// ---------------------------------------------------------------------------
__global__ void zero_kernel(int* deg, int* cursor, float* gsum, int* gcnt,
                            int n_nodes, int n_graphs)
{
    int i = blockIdx.x * blockDim.x + threadIdx.x;
    if (i < n_nodes) { deg[i] = 0; cursor[i] = 0; }
    if (i < n_graphs * GNN_DIM) gsum[i] = 0.f;
    if (i < n_graphs) gcnt[i] = 0;
}

__global__ void hist_count_kernel(const int* __restrict__ dst, int* __restrict__ deg,
                                  const int* __restrict__ nb, int* __restrict__ gcnt,
                                  int n_edges, int n_nodes)
{
    int i = blockIdx.x * blockDim.x + threadIdx.x;
    if (i < n_edges) atomicAdd(&deg[dst[i]], 1);
    if (i < n_nodes) atomicAdd(&gcnt[nb[i]], 1);
}

// ---------------------------------------------------------------------------
// Parallel scan
// ---------------------------------------------------------------------------
__global__ __launch_bounds__(SCAN_BLK) void scan_block_kernel(
    const int* __restrict__ deg, int* __restrict__ rowptr,
    int* __restrict__ bsum, int n)
{
    __shared__ int sm[SCAN_BLK];
    int t = threadIdx.x;
    int i = blockIdx.x * SCAN_BLK + t;
    int v = (i < n) ? deg[i] : 0;
    sm[t] = v;
    __syncthreads();
    #pragma unroll
    for (int off = 1; off < SCAN_BLK; off <<= 1) {
        int u = (t >= off) ? sm[t - off] : 0;
        __syncthreads();
        sm[t] += u;
        __syncthreads();
    }
    if (i < n) rowptr[i] = sm[t] - v;   // exclusive
    if (t == SCAN_BLK - 1) bsum[blockIdx.x] = sm[t];
}

__global__ __launch_bounds__(SCAN_BLK) void scan_fix_kernel(
    const int* __restrict__ bsum, int* __restrict__ rowptr, int n)
{
    __shared__ int s_off;
    int b = blockIdx.x;
    if (threadIdx.x == 0) s_off = 0;
    __syncthreads();
    if (threadIdx.x < b) atomicAdd(&s_off, bsum[threadIdx.x]);
    __syncthreads();
    int i = b * SCAN_BLK + threadIdx.x;
    if (i < n) rowptr[i] += s_off;
}

__global__ void fill_kernel(const int* __restrict__ src, const int* __restrict__ dst,
                            const int* __restrict__ row_ptr, int* __restrict__ cursor,
                            int* __restrict__ csr, int n_edges)
{
    int e = blockIdx.x * blockDim.x + threadIdx.x;
    if (e >= n_edges) return;
    int d = dst[e];
    int pos = atomicAdd(&cursor[d], 1);
    csr[row_ptr[d] + pos] = src[e];
}

// ---------------------------------------------------------------------------
// fp32 -> fp16 convert (for x)
// ---------------------------------------------------------------------------
__global__ void cvt_half_kernel(const float* __restrict__ in, __half* __restrict__ out, int n4)
{
    int i = blockIdx.x * blockDim.x + threadIdx.x;
    if (i >= n4) return;
    float4 v = ((const float4*)in)[i];
    uint2 o;
    *(__half2*)&o.x = __floats2half2_rn(v.x, v.y);
    *(__half2*)&o.y = __floats2half2_rn(v.z, v.w);
    ((uint2*)out)[i] = o;
}

// ---------------------------------------------------------------------------
// fp16 HMMA GEMM core: C[M,N] = A[M,K](fp16) @ W[K,N](fp32, cvt in-flight)
// Block tile 128x64, 8 warps (4x2), warp tile 32x32 via mma.m16n8k16.
// As: half2 [128][12] (k-pairs, pad 12), Bs: half2 [64][12] (B col-major).
// Both fragment-load patterns are bank-conflict-free (stride 12 words).
// ---------------------------------------------------------------------------
struct MmaCtx { int tid, g, ti, warp_m, warp_n; };

__device__ __forceinline__ MmaCtx make_ctx()
{
    MmaCtx c;
    c.tid = threadIdx.x;
    int lane = c.tid & 31;
    int wid  = c.tid >> 5;
    c.g = lane >> 2;
    c.ti = lane & 3;
    c.warp_m = wid & 3;
    c.warp_n = wid >> 2;
    return c;
}

__device__ __forceinline__ void mma16(float c[4], const uint32_t a[4], const uint32_t b[2])
{
    asm volatile(
        "mma.sync.aligned.m16n8k16.row.col.f32.f16.f16.f32 "
        "{%0,%1,%2,%3}, {%4,%5,%6,%7}, {%8,%9}, {%0,%1,%2,%3};"
        : "+f"(c[0]), "+f"(c[1]), "+f"(c[2]), "+f"(c[3])
        : "r"(a[0]), "r"(a[1]), "r"(a[2]), "r"(a[3]), "r"(b[0]), "r"(b[1]));
}

__device__ __forceinline__ void gemm_core_h(
    const __half* __restrict__ A, const float* __restrict__ W,
    int M, int K, int lda, int ldw, int bm, int bn,
    uint32_t (&As)[128][12], uint32_t (&Bs)[64][12],
    const MmaCtx& c, float acc[2][4][4])
{
    const int arow = c.tid >> 1;          // 0..127
    const int ac8  = (c.tid & 1) * 8;     // half offset within 16-half row
    const int wr   = c.tid >> 4;          // 0..15 (k)
    const int wc   = (c.tid & 15) * 4;    // 0..60 (n)
    __half* bsh = (__half*)Bs;            // row stride = 24 halves

    for (int kt = 0; kt < K; kt += 16) {
        {
            int grow = bm + arow;
            uint4 v = make_uint4(0u, 0u, 0u, 0u);
            if (grow < M) v = *(const uint4*)(A + (size_t)grow * lda + kt + ac8);
            *(uint4*)&As[arow][ac8 >> 1] = v;
        }
        {
            float4 v = *(const float4*)(W + (size_t)(kt + wr) * ldw + bn + wc);
            bsh[(wc + 0) * 24 + wr] = __float2half(v.x);
            bsh[(wc + 1) * 24 + wr] = __float2half(v.y);
            bsh[(wc + 2) * 24 + wr] = __float2half(v.z);
            bsh[(wc + 3) * 24 + wr] = __float2half(v.w);
        }
        __syncthreads();

        uint32_t a[2][4], b[4][2];
        #pragma unroll
        for (int mt = 0; mt < 2; mt++) {
            int r0 = c.warp_m * 32 + mt * 16 + c.g;
            a[mt][0] = As[r0][c.ti];
            a[mt][1] = As[r0 + 8][c.ti];
            a[mt][2] = As[r0][c.ti + 4];
            a[mt][3] = As[r0 + 8][c.ti + 4];
        }
        #pragma unroll
        for (int nt = 0; nt < 4; nt++) {
            int n = c.warp_n * 32 + nt * 8 + c.g;
            b[nt][0] = Bs[n][c.ti];
            b[nt][1] = Bs[n][c.ti + 4];
        }
        #pragma unroll
        for (int mt = 0; mt < 2; mt++)
            #pragma unroll
            for (int nt = 0; nt < 4; nt++)
                mma16(acc[mt][nt], a[mt], b[nt]);
        __syncthreads();
    }
}

// ---------------------------------------------------------------------------
// Fused P/Q GEMM (fp16 in/out): blockIdx.y selects W-half (P gets bias)
// ---------------------------------------------------------------------------
__global__ __launch_bounds__(256) void gemm_pq(
    const __half* __restrict__ A,
    const float* __restrict__ Wp, const float* __restrict__ Wq,
    const float* __restrict__ biasp,
    __half* __restrict__ Ph, __half* __restrict__ Qh,
    int M, int N, int K, int lda, int ldw)
{
    __shared__ uint32_t As[128][12];
    __shared__ uint32_t Bs[64][12];

    MmaCtx c = make_ctx();
    const int ntile = N >> 6;
    const int is_q  = (blockIdx.y >= (unsigned)ntile);
    const int bn    = (blockIdx.y - (is_q ? ntile : 0)) * 64;
    const int bm    = blockIdx.x * 128;
    const float* W  = is_q ? Wq : Wp;
    __half* out     = is_q ? Qh : Ph;

    float acc[2][4][4] = {};
    gemm_core_h(A, W, M, K, lda, ldw, bm, bn, As, Bs, c, acc);

    #pragma unroll
    for (int mt = 0; mt < 2; mt++) {
        #pragma unroll
        for (int i = 0; i < 2; i++) {
            int row = bm + c.warp_m * 32 + mt * 16 + c.g + i * 8;
            if (row >= M) continue;
            #pragma unroll
            for (int nt = 0; nt < 4; nt++) {
                int col = bn + c.warp_n * 32 + nt * 8 + c.ti * 2;
                float v0 = acc[mt][nt][i * 2 + 0];
                float v1 = acc[mt][nt][i * 2 + 1];
                if (!is_q) { v0 += biasp[col]; v1 += biasp[col + 1]; }
                *(__half2*)(out + (size_t)row * N + col) = __floats2half2_rn(v0, v1);
            }
        }
    }
}

// ---------------------------------------------------------------------------
// GEMM with epilogue: bias/relu/mask, fp16 C write or pooled fp32 atomics
// ---------------------------------------------------------------------------
#define FLAG_BIAS 1
#define FLAG_RELU 2
#define FLAG_MASK 4
#define FLAG_POOL 8

__global__ __launch_bounds__(256) void gemm_h(
    const __half* __restrict__ A, const float* __restrict__ W,
    const float* __restrict__ bias, const int* __restrict__ deg,
    const int* __restrict__ nb,
    __half* __restrict__ C, float* __restrict__ gsum,
    int M, int N, int K, int lda, int ldw, int ldc, int flags)
{
    __shared__ uint32_t As[128][12];
    __shared__ uint32_t Bs[64][12];

    MmaCtx c = make_ctx();
    const int bm = blockIdx.x * 128;
    const int bn = blockIdx.y * 64;

    float acc[2][4][4] = {};
    gemm_core_h(A, W, M, K, lda, ldw, bm, bn, As, Bs, c, acc);

    #pragma unroll
    for (int mt = 0; mt < 2; mt++) {
        #pragma unroll
        for (int i = 0; i < 2; i++) {
            int row = bm + c.warp_m * 32 + mt * 16 + c.g + i * 8;
            if (row >= M) continue;
            bool zero = (flags & FLAG_MASK) && (deg[row] == 0);
            int batch = (flags & FLAG_POOL) ? nb[row] : 0;
            #pragma unroll
            for (int nt = 0; nt < 4; nt++) {
                int col = bn + c.warp_n * 32 + nt * 8 + c.ti * 2;
                float v0 = acc[mt][nt][i * 2 + 0];
                float v1 = acc[mt][nt][i * 2 + 1];
                if (flags & FLAG_BIAS) { v0 += bias[col]; v1 += bias[col + 1]; }
                if (flags & FLAG_RELU) { v0 = fmaxf(v0, 0.f); v1 = fmaxf(v1, 0.f); }
                if (zero) { v0 = 0.f; v1 = 0.f; }
                if (flags & FLAG_POOL) {
                    atomicAdd(&gsum[batch * GNN_DIM + col],     v0);
                    atomicAdd(&gsum[batch * GNN_DIM + col + 1], v1);
                } else {
                    *(__half2*)(C + (size_t)row * ldc + col) = __floats2half2_rn(v0, v1);
                }
            }
        }
    }
}

// ---------------------------------------------------------------------------
// Edge gather-reduce (all fp16): S[n] = mean_{e:dst=n} relu(P[n]+Q[src_e])
// ---------------------------------------------------------------------------
template <int LANES>
__global__ void gather_h2_kernel(
    const __half* __restrict__ P, const __half* __restrict__ Q,
    const int* __restrict__ row_ptr, const int* __restrict__ deg,
    const int* __restrict__ csr, __half* __restrict__ S, int n_nodes)
{
    const int FEAT = LANES * 8;
    int gid  = blockIdx.x * blockDim.x + threadIdx.x;
    int node = gid / LANES;
    int sub  = gid % LANES;
    if (node >= n_nodes) return;

    uint4 pv = *(const uint4*)(P + (size_t)node * FEAT + sub * 8);
    __half2 p0 = *(__half2*)&pv.x, p1 = *(__half2*)&pv.y;
    __half2 p2 = *(__half2*)&pv.z, p3 = *(__half2*)&pv.w;

    const __half2 z2 = __float2half2_rn(0.f);
    __half2 a0 = z2, a1 = z2, a2 = z2, a3 = z2;

    int start = row_ptr[node];
    int d     = deg[node];

    if (d > 0) {
        int s = csr[start];
        uint4 qv = *(const uint4*)(Q + (size_t)s * FEAT + sub * 8);
        for (int i = 0; i < d; i++) {
            uint4 qn = qv;
            if (i + 1 < d) {
                int sn = csr[start + i + 1];
                qn = *(const uint4*)(Q + (size_t)sn * FEAT + sub * 8);
            }
            a0 = __hadd2(a0, __hmax2(__hadd2(p0, *(__half2*)&qv.x), z2));
            a1 = __hadd2(a1, __hmax2(__hadd2(p1, *(__half2*)&qv.y), z2));
            a2 = __hadd2(a2, __hmax2(__hadd2(p2, *(__half2*)&qv.z), z2));
            a3 = __hadd2(a3, __hmax2(__hadd2(p3, *(__half2*)&qv.w), z2));
            qv = qn;
        }
    }

    float inv = 1.0f / (float)(d > 0 ? d : 1);
    float2 f0 = __half22float2(a0), f1 = __half22float2(a1);
    float2 f2 = __half22float2(a2), f3 = __half22float2(a3);
    uint4 o;
    *(__half2*)&o.x = __floats2half2_rn(f0.x * inv, f0.y * inv);
    *(__half2*)&o.y = __floats2half2_rn(f1.x * inv, f1.y * inv);
    *(__half2*)&o.z = __floats2half2_rn(f2.x * inv, f2.y * inv);
    *(__half2*)&o.w = __floats2half2_rn(f3.x * inv, f3.y * inv);
    *(uint4*)(S + (size_t)node * FEAT + sub * 8) = o;
}

// ---------------------------------------------------------------------------
// Actor head (one block per graph)
// ---------------------------------------------------------------------------
__global__ __launch_bounds__(256) void head_kernel(
    const float* __restrict__ state,
    const float* __restrict__ gsum, const int* __restrict__ gcnt,
    const float* __restrict__ fc1_w, const float* __restrict__ fc1_b,
    const float* __restrict__ fc2_w, const float* __restrict__ fc2_b,
    const float* __restrict__ mean_w, const float* __restrict__ mean_b,
    const float* __restrict__ ls_w, const float* __restrict__ ls_b,
    float* __restrict__ out, int n_graphs)
{
    __shared__ float z[128];
    __shared__ float h1[256];
    __shared__ float h2[256];
    int b = blockIdx.x;
    int t = threadIdx.x;
    if (b >= n_graphs) return;

    if (t < 64) {
        z[t] = state[b * 64 + t];
    } else if (t < 128) {
        float c = fmaxf((float)gcnt[b], 1.f);
        z[t] = gsum[b * GNN_DIM + (t - 64)] / c;
    }
    __syncthreads();

    {
        float s = fc1_b[t];
        #pragma unroll 4
        for (int k = 0; k < 128; k++) s += z[k] * fc1_w[k * 256 + t];
        h1[t] = fmaxf(s, 0.f);
    }
    __syncthreads();
    {
        float s = fc2_b[t];
        #pragma unroll 4
        for (int k = 0; k < 256; k++) s += h1[k] * fc2_w[k * 256 + t];
        h2[t] = fmaxf(s, 0.f);
    }
    __syncthreads();

    if (t < ACTION_DIM) {
        float s = mean_b[t];
        #pragma unroll 4
        for (int k = 0; k < 256; k++) s += h2[k] * mean_w[k * ACTION_DIM + t];
        out[b * ACTION_DIM + t] = s;
    } else if (t < 2 * ACTION_DIM) {
        int j = t - ACTION_DIM;
        float s = ls_b[j];
        #pragma unroll 4
        for (int k = 0; k < 256; k++) s += h2[k] * ls_w[k * ACTION_DIM + j];
        s = fminf(fmaxf(s, -20.f), 2.f);
        out[n_graphs * ACTION_DIM + b * ACTION_DIM + j] = s;
    }
}

// ---------------------------------------------------------------------------
// Launch
// ---------------------------------------------------------------------------
extern "C" void kernel_launch(void* const* d_in, const int* in_sizes, int n_in,
                              void* d_out, int out_size)
{
    const float* state  = (const float*)d_in[0];
    const float* x      = (const float*)d_in[1];
    const int*   eidx   = (const int*)  d_in[2];
    const int*   nbatch = (const int*)  d_in[3];
    const float* g1w1   = (const float*)d_in[4];
    const float* g1b1   = (const float*)d_in[5];
    const float* g1w2   = (const float*)d_in[6];
    const float* g1b2   = (const float*)d_in[7];
    const float* g2w1   = (const float*)d_in[8];
    const float* g2b1   = (const float*)d_in[9];
    const float* g2w2   = (const float*)d_in[10];
    const float* g2b2   = (const float*)d_in[11];
    const float* fc1_w  = (const float*)d_in[12];
    const float* fc1_b  = (const float*)d_in[13];
    const float* fc2_w  = (const float*)d_in[14];
    const float* fc2_b  = (const float*)d_in[15];
    const float* mean_w = (const float*)d_in[16];
    const float* mean_b = (const float*)d_in[17];
    const float* ls_w   = (const float*)d_in[18];
    const float* ls_b   = (const float*)d_in[19];
    float* out = (float*)d_out;

    const int n_graphs = in_sizes[0] / 64;
    const int n_nodes  = in_sizes[1] / NODE_DIM;
    const int n_edges  = in_sizes[2] / 2;
    const int* e_src = eidx;
    const int* e_dst = eidx + n_edges;

    __half *bufXh, *bufPh, *bufQh, *bufSh, *bufHh;
    float *gsum;
    int *deg, *cursor, *rowptr, *csr, *gcnt, *bsum;
    cudaGetSymbolAddress((void**)&bufXh,  g_bufXh);
    cudaGetSymbolAddress((void**)&bufPh,  g_bufPh);
    cudaGetSymbolAddress((void**)&bufQh,  g_bufQh);
    cudaGetSymbolAddress((void**)&bufSh,  g_bufSh);
    cudaGetSymbolAddress((void**)&bufHh,  g_bufHh);
    cudaGetSymbolAddress((void**)&deg,    g_deg);
    cudaGetSymbolAddress((void**)&cursor, g_cursor);
    cudaGetSymbolAddress((void**)&rowptr, g_rowptr);
    cudaGetSymbolAddress((void**)&csr,    g_csr);
    cudaGetSymbolAddress((void**)&bsum,   g_bsum);
    cudaGetSymbolAddress((void**)&gsum,   g_gsum);
    cudaGetSymbolAddress((void**)&gcnt,   g_gcnt);

    // init + CSR build + x convert
    zero_kernel<<<(n_nodes + 255) / 256, 256>>>(deg, cursor, gsum, gcnt, n_nodes, n_graphs);
    int eblocks = (n_edges + 255) / 256;
    hist_count_kernel<<<eblocks, 256>>>(e_dst, deg, nbatch, gcnt, n_edges, n_nodes);
    int sblocks = (n_nodes + SCAN_BLK - 1) / SCAN_BLK;
    scan_block_kernel<<<sblocks, SCAN_BLK>>>(deg, rowptr, bsum, n_nodes);
    scan_fix_kernel<<<sblocks, SCAN_BLK>>>(bsum, rowptr, n_nodes);
    fill_kernel<<<eblocks, 256>>>(e_src, e_dst, rowptr, cursor, csr, n_edges);
    cvt_half_kernel<<<(n_nodes * NODE_DIM / 4 + 255) / 256, 256>>>(x, bufXh, n_nodes * NODE_DIM / 4);

    const int mb = (n_nodes + 127) / 128;

    // ---- GNN layer 1 ----
    gemm_pq<<<dim3(mb, 4), 256>>>(bufXh, g1w1, g1w1 + 64 * 128, g1b1,
                                  bufPh, bufQh, n_nodes, 128, 64, 64, 128);
    gather_h2_kernel<16><<<(n_nodes * 16 + 255) / 256, 256>>>(
        bufPh, bufQh, rowptr, deg, csr, bufSh, n_nodes);
    gemm_h<<<dim3(mb, 2), 256>>>(bufSh, g1w2, g1b2, deg, nbatch,
                                 bufHh, gsum,
                                 n_nodes, 128, 128, 128, 128, 128,
                                 FLAG_BIAS | FLAG_RELU | FLAG_MASK);

    // ---- GNN layer 2 ----
    gemm_pq<<<dim3(mb, 2), 256>>>(bufHh, g2w1, g2w1 + 128 * 64, g2b1,
                                  bufPh, bufQh, n_nodes, 64, 128, 128, 64);
    gather_h2_kernel<8><<<(n_nodes * 8 + 255) / 256, 256>>>(
        bufPh, bufQh, rowptr, deg, csr, bufSh, n_nodes);
    gemm_h<<<dim3(mb, 1), 256>>>(bufSh, g2w2, g2b2, deg, nbatch,
                                 nullptr, gsum,
                                 n_nodes, 64, 64, 64, 64, 64,
                                 FLAG_BIAS | FLAG_MASK | FLAG_POOL);

    // ---- head ----
    head_kernel<<<n_graphs, 256>>>(state, gsum, gcnt,
                                   fc1_w, fc1_b, fc2_w, fc2_b,
                                   mean_w, mean_b, ls_w, ls_b,
                                   out, n_graphs);
}

// round 5
// speedup vs baseline: 1.7401x; 1.0600x over previous
#include <cuda_runtime.h>
#include <cuda_fp16.h>
#include <cstdint>

// ---------------------------------------------------------------------------
// Problem constants
// ---------------------------------------------------------------------------
#define MAX_NODES 50000
#define MAX_EDGES 800000
#define NODE_DIM  64
#define GNN_H     128
#define GNN_DIM   64
#define NB        128
#define HIDDEN    256
#define ACTION_DIM 8
#define SCAN_BLK  1024
#define SBLOCKS_MAX ((MAX_NODES + SCAN_BLK - 1) / SCAN_BLK)

// ---------------------------------------------------------------------------
// Device scratch
// ---------------------------------------------------------------------------
__device__ __half g_bufXh[MAX_NODES * NODE_DIM];
__device__ __half g_bufPh[MAX_NODES * GNN_H];
__device__ __half g_bufQh[MAX_NODES * GNN_H];
__device__ __half g_bufSh[MAX_NODES * GNN_H];
__device__ int    g_deg[MAX_NODES];
__device__ int    g_cursor[MAX_NODES];
__device__ int    g_rowptr[MAX_NODES];
__device__ int    g_csr[MAX_EDGES];
__device__ int    g_agg[SBLOCKS_MAX];
__device__ int    g_flag[SBLOCKS_MAX];
__device__ float  g_gsum[NB * GNN_DIM];
__device__ int    g_gcnt[NB];

// ---------------------------------------------------------------------------
// init: zero counters + convert x to fp16 (fused)
// ---------------------------------------------------------------------------
__global__ void init_kernel(const float* __restrict__ x, __half* __restrict__ xh,
                            int* __restrict__ deg, float* __restrict__ gsum,
                            int* __restrict__ gcnt, int* __restrict__ flag,
                            int n_nodes, int n_graphs, int ncvt)
{
    int i = blockIdx.x * blockDim.x + threadIdx.x;
    if (i < ncvt) {
        float4 v = ((const float4*)x)[i];
        uint2 o;
        *(__half2*)&o.x = __floats2half2_rn(v.x, v.y);
        *(__half2*)&o.y = __floats2half2_rn(v.z, v.w);
        ((uint2*)xh)[i] = o;
    }
    if (i < n_nodes) deg[i] = 0;
    if (i < n_graphs * GNN_DIM) gsum[i] = 0.f;
    if (i < n_graphs) gcnt[i] = 0;
    if (i < SBLOCKS_MAX) flag[i] = 0;
}

__global__ void hist_count_kernel(const int* __restrict__ dst, int* __restrict__ deg,
                                  const int* __restrict__ nb, int* __restrict__ gcnt,
                                  int n_edges, int n_nodes)
{
    int i = blockIdx.x * blockDim.x + threadIdx.x;
    if (i < n_edges) atomicAdd(&deg[dst[i]], 1);
    if (i < n_nodes) atomicAdd(&gcnt[nb[i]], 1);
}

// ---------------------------------------------------------------------------
// Single-kernel scan: block-local Hillis-Steele + warp-parallel lookback.
// All blocks (<=49) are co-resident; block b only waits on j<b -> no deadlock.
// Writes rowptr AND cursor (cursor consumed destructively by fill).
// ---------------------------------------------------------------------------
__global__ __launch_bounds__(SCAN_BLK) void scan_lb_kernel(
    const int* __restrict__ deg, int* __restrict__ rowptr, int* __restrict__ cursor,
    int* __restrict__ agg, int* __restrict__ flag, int n)
{
    __shared__ int sm[SCAN_BLK];
    __shared__ int s_run;
    int t = threadIdx.x, b = blockIdx.x;
    int i = b * SCAN_BLK + t;
    int v = (i < n) ? deg[i] : 0;
    sm[t] = v;
    __syncthreads();
    #pragma unroll
    for (int off = 1; off < SCAN_BLK; off <<= 1) {
        int u = (t >= off) ? sm[t - off] : 0;
        __syncthreads();
        sm[t] += u;
        __syncthreads();
    }
    if (t == 0) {
        agg[b] = sm[SCAN_BLK - 1];
        __threadfence();
        atomicExch(&flag[b], 1);
    }
    if (t < 32) {
        int run = 0;
        for (int j = t; j < b; j += 32) {
            while (atomicAdd(&flag[j], 0) == 0) { }
            __threadfence();
            run += *(volatile const int*)&agg[j];
        }
        #pragma unroll
        for (int off = 16; off; off >>= 1)
            run += __shfl_down_sync(0xffffffffu, run, off);
        if (t == 0) s_run = run;
    }
    __syncthreads();
    if (i < n) {
        int r = s_run + sm[t] - v;   // exclusive
        rowptr[i] = r;
        cursor[i] = r;
    }
}

// fill: atomics directly on cursor (pre-seeded with rowptr)
__global__ void fill_kernel(const int* __restrict__ src, const int* __restrict__ dst,
                            int* __restrict__ cursor, int* __restrict__ csr, int n_edges)
{
    int e = blockIdx.x * blockDim.x + threadIdx.x;
    if (e >= n_edges) return;
    int pos = atomicAdd(&cursor[dst[e]], 1);
    csr[pos] = src[e];
}

// ---------------------------------------------------------------------------
// fp16 HMMA GEMM core (as R4): block tile 128x64, 8 warps 4x2, warp 32x32.
// ---------------------------------------------------------------------------
struct MmaCtx { int tid, g, ti, warp_m, warp_n; };

__device__ __forceinline__ MmaCtx make_ctx()
{
    MmaCtx c;
    c.tid = threadIdx.x;
    int lane = c.tid & 31;
    int wid  = c.tid >> 5;
    c.g = lane >> 2;
    c.ti = lane & 3;
    c.warp_m = wid & 3;
    c.warp_n = wid >> 2;
    return c;
}

__device__ __forceinline__ void mma16(float c[4], const uint32_t a[4], const uint32_t b[2])
{
    asm volatile(
        "mma.sync.aligned.m16n8k16.row.col.f32.f16.f16.f32 "
        "{%0,%1,%2,%3}, {%4,%5,%6,%7}, {%8,%9}, {%0,%1,%2,%3};"
        : "+f"(c[0]), "+f"(c[1]), "+f"(c[2]), "+f"(c[3])
        : "r"(a[0]), "r"(a[1]), "r"(a[2]), "r"(a[3]), "r"(b[0]), "r"(b[1]));
}

__device__ __forceinline__ void gemm_core_h(
    const __half* __restrict__ A, const float* __restrict__ W,
    int M, int K, int lda, int ldw, int bm, int bn,
    uint32_t (&As)[128][12], uint32_t (&Bs)[64][12],
    const MmaCtx& c, float acc[2][4][4])
{
    const int arow = c.tid >> 1;
    const int ac8  = (c.tid & 1) * 8;
    const int wr   = c.tid >> 4;
    const int wc   = (c.tid & 15) * 4;
    __half* bsh = (__half*)Bs;

    for (int kt = 0; kt < K; kt += 16) {
        {
            int grow = bm + arow;
            uint4 v = make_uint4(0u, 0u, 0u, 0u);
            if (grow < M) v = *(const uint4*)(A + (size_t)grow * lda + kt + ac8);
            *(uint4*)&As[arow][ac8 >> 1] = v;
        }
        {
            float4 v = *(const float4*)(W + (size_t)(kt + wr) * ldw + bn + wc);
            bsh[(wc + 0) * 24 + wr] = __float2half(v.x);
            bsh[(wc + 1) * 24 + wr] = __float2half(v.y);
            bsh[(wc + 2) * 24 + wr] = __float2half(v.z);
            bsh[(wc + 3) * 24 + wr] = __float2half(v.w);
        }
        __syncthreads();

        uint32_t a[2][4], b[4][2];
        #pragma unroll
        for (int mt = 0; mt < 2; mt++) {
            int r0 = c.warp_m * 32 + mt * 16 + c.g;
            a[mt][0] = As[r0][c.ti];
            a[mt][1] = As[r0 + 8][c.ti];
            a[mt][2] = As[r0][c.ti + 4];
            a[mt][3] = As[r0 + 8][c.ti + 4];
        }
        #pragma unroll
        for (int nt = 0; nt < 4; nt++) {
            int n = c.warp_n * 32 + nt * 8 + c.g;
            b[nt][0] = Bs[n][c.ti];
            b[nt][1] = Bs[n][c.ti + 4];
        }
        #pragma unroll
        for (int mt = 0; mt < 2; mt++)
            #pragma unroll
            for (int nt = 0; nt < 4; nt++)
                mma16(acc[mt][nt], a[mt], b[nt]);
        __syncthreads();
    }
}

// ---------------------------------------------------------------------------
// Layer-1 P/Q GEMM (fp16 in/out): blockIdx.y selects W-half (P gets bias)
// ---------------------------------------------------------------------------
__global__ __launch_bounds__(256) void gemm_pq(
    const __half* __restrict__ A,
    const float* __restrict__ Wp, const float* __restrict__ Wq,
    const float* __restrict__ biasp,
    __half* __restrict__ Ph, __half* __restrict__ Qh,
    int M, int N, int K, int lda, int ldw)
{
    __shared__ uint32_t As[128][12];
    __shared__ uint32_t Bs[64][12];

    MmaCtx c = make_ctx();
    const int ntile = N >> 6;
    const int is_q  = (blockIdx.y >= (unsigned)ntile);
    const int bn    = (blockIdx.y - (is_q ? ntile : 0)) * 64;
    const int bm    = blockIdx.x * 128;
    const float* W  = is_q ? Wq : Wp;
    __half* out     = is_q ? Qh : Ph;

    float acc[2][4][4] = {};
    gemm_core_h(A, W, M, K, lda, ldw, bm, bn, As, Bs, c, acc);

    #pragma unroll
    for (int mt = 0; mt < 2; mt++) {
        #pragma unroll
        for (int i = 0; i < 2; i++) {
            int row = bm + c.warp_m * 32 + mt * 16 + c.g + i * 8;
            if (row >= M) continue;
            #pragma unroll
            for (int nt = 0; nt < 4; nt++) {
                int col = bn + c.warp_n * 32 + nt * 8 + c.ti * 2;
                float v0 = acc[mt][nt][i * 2 + 0];
                float v1 = acc[mt][nt][i * 2 + 1];
                if (!is_q) { v0 += biasp[col]; v1 += biasp[col + 1]; }
                *(__half2*)(out + (size_t)row * N + col) = __floats2half2_rn(v0, v1);
            }
        }
    }
}

// ---------------------------------------------------------------------------
// FUSED: H1 = relu(mask(S @ W1 + b1)) kept in smem (fp16, 128x128), then
// P2 = H1 @ W2[:128] + b2, Q2 = H1 @ W2[128:]. H1 never touches global.
// ---------------------------------------------------------------------------
__global__ __launch_bounds__(256) void gemm_h1pq2(
    const __half* __restrict__ S,
    const float* __restrict__ W1, const float* __restrict__ b1,
    const float* __restrict__ W2, const float* __restrict__ b2,
    const int* __restrict__ deg,
    __half* __restrict__ P2, __half* __restrict__ Q2, int M)
{
    __shared__ uint32_t As[128][12];
    __shared__ uint32_t Bs[64][12];
    __shared__ uint32_t Ts[128][68];   // H1 tile: 128 rows x 64 half2-pairs (+4 pad)

    MmaCtx c = make_ctx();
    const int bm = blockIdx.x * 128;

    // ---- stage 1: H1 tile into Ts ----
    #pragma unroll
    for (int half = 0; half < 2; half++) {
        int bn = half * 64;
        float acc[2][4][4] = {};
        gemm_core_h(S, W1, M, 128, 128, 128, bm, bn, As, Bs, c, acc);
        #pragma unroll
        for (int mt = 0; mt < 2; mt++) {
            #pragma unroll
            for (int i = 0; i < 2; i++) {
                int row  = c.warp_m * 32 + mt * 16 + c.g + i * 8;
                int grow = bm + row;
                bool zero = (grow >= M) || (deg[grow < M ? grow : 0] == 0);
                #pragma unroll
                for (int nt = 0; nt < 4; nt++) {
                    int col = bn + c.warp_n * 32 + nt * 8 + c.ti * 2;
                    float v0 = acc[mt][nt][i * 2 + 0] + b1[col];
                    float v1 = acc[mt][nt][i * 2 + 1] + b1[col + 1];
                    v0 = fmaxf(v0, 0.f); v1 = fmaxf(v1, 0.f);
                    if (zero) { v0 = 0.f; v1 = 0.f; }
                    __half2 h = __floats2half2_rn(v0, v1);
                    Ts[row][col >> 1] = *(uint32_t*)&h;
                }
            }
        }
    }
    __syncthreads();

    // ---- stage 2: P2/Q2 from Ts ----
    const int wr = c.tid >> 4;
    const int wc = (c.tid & 15) * 4;
    __half* bsh = (__half*)Bs;

    #pragma unroll
    for (int half = 0; half < 2; half++) {
        const float* W = W2 + (size_t)half * 128 * 64;
        __half* out = half ? Q2 : P2;
        float acc[2][4][4] = {};
        for (int kt = 0; kt < 128; kt += 16) {
            {
                float4 v = *(const float4*)(W + (size_t)(kt + wr) * 64 + wc);
                bsh[(wc + 0) * 24 + wr] = __float2half(v.x);
                bsh[(wc + 1) * 24 + wr] = __float2half(v.y);
                bsh[(wc + 2) * 24 + wr] = __float2half(v.z);
                bsh[(wc + 3) * 24 + wr] = __float2half(v.w);
            }
            __syncthreads();
            uint32_t a[2][4], b[4][2];
            int kc = kt >> 1;
            #pragma unroll
            for (int mt = 0; mt < 2; mt++) {
                int r0 = c.warp_m * 32 + mt * 16 + c.g;
                a[mt][0] = Ts[r0][kc + c.ti];
                a[mt][1] = Ts[r0 + 8][kc + c.ti];
                a[mt][2] = Ts[r0][kc + c.ti + 4];
                a[mt][3] = Ts[r0 + 8][kc + c.ti + 4];
            }
            #pragma unroll
            for (int nt = 0; nt < 4; nt++) {
                int n = c.warp_n * 32 + nt * 8 + c.g;
                b[nt][0] = Bs[n][c.ti];
                b[nt][1] = Bs[n][c.ti + 4];
            }
            #pragma unroll
            for (int mt = 0; mt < 2; mt++)
                #pragma unroll
                for (int nt = 0; nt < 4; nt++)
                    mma16(acc[mt][nt], a[mt], b[nt]);
            __syncthreads();
        }
        #pragma unroll
        for (int mt = 0; mt < 2; mt++) {
            #pragma unroll
            for (int i = 0; i < 2; i++) {
                int row = bm + c.warp_m * 32 + mt * 16 + c.g + i * 8;
                if (row >= M) continue;
                #pragma unroll
                for (int nt = 0; nt < 4; nt++) {
                    int col = c.warp_n * 32 + nt * 8 + c.ti * 2;
                    float v0 = acc[mt][nt][i * 2 + 0];
                    float v1 = acc[mt][nt][i * 2 + 1];
                    if (!half) { v0 += b2[col]; v1 += b2[col + 1]; }
                    *(__half2*)(out + (size_t)row * 64 + col) = __floats2half2_rn(v0, v1);
                }
            }
        }
    }
}

// ---------------------------------------------------------------------------
// GEMM with epilogue: bias/mask, pooled fp32 atomics (H2 layer)
// ---------------------------------------------------------------------------
__global__ __launch_bounds__(256) void gemm_h2pool(
    const __half* __restrict__ A, const float* __restrict__ W,
    const float* __restrict__ bias, const int* __restrict__ deg,
    const int* __restrict__ nb, float* __restrict__ gsum,
    int M, int N, int K, int lda, int ldw)
{
    __shared__ uint32_t As[128][12];
    __shared__ uint32_t Bs[64][12];

    MmaCtx c = make_ctx();
    const int bm = blockIdx.x * 128;

    float acc[2][4][4] = {};
    gemm_core_h(A, W, M, K, lda, ldw, bm, 0, As, Bs, c, acc);

    #pragma unroll
    for (int mt = 0; mt < 2; mt++) {
        #pragma unroll
        for (int i = 0; i < 2; i++) {
            int row = bm + c.warp_m * 32 + mt * 16 + c.g + i * 8;
            if (row >= M) continue;
            bool zero = (deg[row] == 0);
            int batch = nb[row];
            #pragma unroll
            for (int nt = 0; nt < 4; nt++) {
                int col = c.warp_n * 32 + nt * 8 + c.ti * 2;
                float v0 = acc[mt][nt][i * 2 + 0] + bias[col];
                float v1 = acc[mt][nt][i * 2 + 1] + bias[col + 1];
                if (zero) { v0 = 0.f; v1 = 0.f; }
                atomicAdd(&gsum[batch * GNN_DIM + col],     v0);
                atomicAdd(&gsum[batch * GNN_DIM + col + 1], v1);
            }
        }
    }
}

// ---------------------------------------------------------------------------
// Gather: warp-per-node. CSR loaded 32 entries at a time (coalesced) and
// distributed via shfl. EPI edges processed per warp-iteration with depth-2
// prefetch. Cross-eslot reduction via shfl_xor.
// ---------------------------------------------------------------------------
__device__ __forceinline__ __half2 h2add(__half2 a, __half2 b) { return __hadd2(a, b); }

template <int FEAT>
__global__ __launch_bounds__(256) void gather_warp_kernel(
    const __half* __restrict__ P, const __half* __restrict__ Q,
    const int* __restrict__ row_ptr, const int* __restrict__ deg,
    const int* __restrict__ csr, __half* __restrict__ S, int n_nodes)
{
    constexpr int HALFL = FEAT / 8;            // lanes covering one row
    constexpr int SHIFT = (HALFL == 16) ? 4 : 3;
    constexpr int EPI   = 32 / HALFL;          // edges in flight per warp-iter

    int node = (blockIdx.x * blockDim.x + threadIdx.x) >> 5;
    if (node >= n_nodes) return;
    int lane  = threadIdx.x & 31;
    int sub   = lane & (HALFL - 1);
    int eslot = lane >> SHIFT;

    uint4 pv = *(const uint4*)(P + (size_t)node * FEAT + sub * 8);
    __half2 p0 = *(__half2*)&pv.x, p1 = *(__half2*)&pv.y;
    __half2 p2 = *(__half2*)&pv.z, p3 = *(__half2*)&pv.w;

    const __half2 z2 = __float2half2_rn(0.f);
    __half2 a0 = z2, a1 = z2, a2 = z2, a3 = z2;

    int d     = deg[node];
    int start = row_ptr[node];

    for (int base = 0; base < d; base += 32) {
        int cnt = min(d - base, 32);
        int sidx = 0;
        if (lane < cnt) sidx = csr[start + base + lane];
        int iters = (cnt + EPI - 1) / EPI;

        int  i   = eslot;
        bool act = i < cnt;
        int  s   = __shfl_sync(0xffffffffu, sidx, i & 31);
        uint4 qv = make_uint4(0u, 0u, 0u, 0u);
        if (act) qv = *(const uint4*)(Q + (size_t)s * FEAT + sub * 8);

        for (int it = 1; it <= iters; it++) {
            int  i2   = it * EPI + eslot;
            bool act2 = i2 < cnt;
            int  s2   = __shfl_sync(0xffffffffu, sidx, i2 & 31);
            uint4 qn  = make_uint4(0u, 0u, 0u, 0u);
            if (act2) qn = *(const uint4*)(Q + (size_t)s2 * FEAT + sub * 8);
            if (act) {
                a0 = h2add(a0, __hmax2(h2add(p0, *(__half2*)&qv.x), z2));
                a1 = h2add(a1, __hmax2(h2add(p1, *(__half2*)&qv.y), z2));
                a2 = h2add(a2, __hmax2(h2add(p2, *(__half2*)&qv.z), z2));
                a3 = h2add(a3, __hmax2(h2add(p3, *(__half2*)&qv.w), z2));
            }
            qv = qn; act = act2;
        }
    }

    // reduce accumulators across eslots
    #pragma unroll
    for (int off = HALFL; off < 32; off <<= 1) {
        uint32_t u;
        u = __shfl_xor_sync(0xffffffffu, *(uint32_t*)&a0, off); a0 = h2add(a0, *(__half2*)&u);
        u = __shfl_xor_sync(0xffffffffu, *(uint32_t*)&a1, off); a1 = h2add(a1, *(__half2*)&u);
        u = __shfl_xor_sync(0xffffffffu, *(uint32_t*)&a2, off); a2 = h2add(a2, *(__half2*)&u);
        u = __shfl_xor_sync(0xffffffffu, *(uint32_t*)&a3, off); a3 = h2add(a3, *(__half2*)&u);
    }

    if (eslot == 0) {
        float inv = 1.0f / (float)(d > 0 ? d : 1);
        float2 f0 = __half22float2(a0), f1 = __half22float2(a1);
        float2 f2 = __half22float2(a2), f3 = __half22float2(a3);
        uint4 o;
        *(__half2*)&o.x = __floats2half2_rn(f0.x * inv, f0.y * inv);
        *(__half2*)&o.y = __floats2half2_rn(f1.x * inv, f1.y * inv);
        *(__half2*)&o.z = __floats2half2_rn(f2.x * inv, f2.y * inv);
        *(__half2*)&o.w = __floats2half2_rn(f3.x * inv, f3.y * inv);
        *(uint4*)(S + (size_t)node * FEAT + sub * 8) = o;
    }
}

// ---------------------------------------------------------------------------
// Actor head (one block per graph)
// ---------------------------------------------------------------------------
__global__ __launch_bounds__(256) void head_kernel(
    const float* __restrict__ state,
    const float* __restrict__ gsum, const int* __restrict__ gcnt,
    const float* __restrict__ fc1_w, const float* __restrict__ fc1_b,
    const float* __restrict__ fc2_w, const float* __restrict__ fc2_b,
    const float* __restrict__ mean_w, const float* __restrict__ mean_b,
    const float* __restrict__ ls_w, const float* __restrict__ ls_b,
    float* __restrict__ out, int n_graphs)
{
    __shared__ float z[128];
    __shared__ float h1[256];
    __shared__ float h2[256];
    int b = blockIdx.x;
    int t = threadIdx.x;
    if (b >= n_graphs) return;

    if (t < 64) {
        z[t] = state[b * 64 + t];
    } else if (t < 128) {
        float c = fmaxf((float)gcnt[b], 1.f);
        z[t] = gsum[b * GNN_DIM + (t - 64)] / c;
    }
    __syncthreads();

    {
        float s = fc1_b[t];
        #pragma unroll 4
        for (int k = 0; k < 128; k++) s += z[k] * fc1_w[k * 256 + t];
        h1[t] = fmaxf(s, 0.f);
    }
    __syncthreads();
    {
        float s = fc2_b[t];
        #pragma unroll 4
        for (int k = 0; k < 256; k++) s += h1[k] * fc2_w[k * 256 + t];
        h2[t] = fmaxf(s, 0.f);
    }
    __syncthreads();

    if (t < ACTION_DIM) {
        float s = mean_b[t];
        #pragma unroll 4
        for (int k = 0; k < 256; k++) s += h2[k] * mean_w[k * ACTION_DIM + t];
        out[b * ACTION_DIM + t] = s;
    } else if (t < 2 * ACTION_DIM) {
        int j = t - ACTION_DIM;
        float s = ls_b[j];
        #pragma unroll 4
        for (int k = 0; k < 256; k++) s += h2[k] * ls_w[k * ACTION_DIM + j];
        s = fminf(fmaxf(s, -20.f), 2.f);
        out[n_graphs * ACTION_DIM + b * ACTION_DIM + j] = s;
    }
}

// ---------------------------------------------------------------------------
// Launch
// ---------------------------------------------------------------------------
extern "C" void kernel_launch(void* const* d_in, const int* in_sizes, int n_in,
                              void* d_out, int out_size)
{
    const float* state  = (const float*)d_in[0];
    const float* x      = (const float*)d_in[1];
    const int*   eidx   = (const int*)  d_in[2];
    const int*   nbatch = (const int*)  d_in[3];
    const float* g1w1   = (const float*)d_in[4];
    const float* g1b1   = (const float*)d_in[5];
    const float* g1w2   = (const float*)d_in[6];
    const float* g1b2   = (const float*)d_in[7];
    const float* g2w1   = (const float*)d_in[8];
    const float* g2b1   = (const float*)d_in[9];
    const float* g2w2   = (const float*)d_in[10];
    const float* g2b2   = (const float*)d_in[11];
    const float* fc1_w  = (const float*)d_in[12];
    const float* fc1_b  = (const float*)d_in[13];
    const float* fc2_w  = (const float*)d_in[14];
    const float* fc2_b  = (const float*)d_in[15];
    const float* mean_w = (const float*)d_in[16];
    const float* mean_b = (const float*)d_in[17];
    const float* ls_w   = (const float*)d_in[18];
    const float* ls_b   = (const float*)d_in[19];
    float* out = (float*)d_out;

    const int n_graphs = in_sizes[0] / 64;
    const int n_nodes  = in_sizes[1] / NODE_DIM;
    const int n_edges  = in_sizes[2] / 2;
    const int* e_src = eidx;
    const int* e_dst = eidx + n_edges;

    __half *bufXh, *bufPh, *bufQh, *bufSh;
    float *gsum;
    int *deg, *cursor, *rowptr, *csr, *gcnt, *agg, *flag;
    cudaGetSymbolAddress((void**)&bufXh,  g_bufXh);
    cudaGetSymbolAddress((void**)&bufPh,  g_bufPh);
    cudaGetSymbolAddress((void**)&bufQh,  g_bufQh);
    cudaGetSymbolAddress((void**)&bufSh,  g_bufSh);
    cudaGetSymbolAddress((void**)&deg,    g_deg);
    cudaGetSymbolAddress((void**)&cursor, g_cursor);
    cudaGetSymbolAddress((void**)&rowptr, g_rowptr);
    cudaGetSymbolAddress((void**)&csr,    g_csr);
    cudaGetSymbolAddress((void**)&agg,    g_agg);
    cudaGetSymbolAddress((void**)&flag,   g_flag);
    cudaGetSymbolAddress((void**)&gsum,   g_gsum);
    cudaGetSymbolAddress((void**)&gcnt,   g_gcnt);

    const int ncvt = n_nodes * NODE_DIM / 4;
    const int mb = (n_nodes + 127) / 128;
    const int eblocks = (n_edges + 255) / 256;
    const int sblocks = (n_nodes + SCAN_BLK - 1) / SCAN_BLK;
    const int gblocks = (n_nodes * 32 + 255) / 256;

    // (1) init: zero + x->fp16
    init_kernel<<<(ncvt + 255) / 256, 256>>>(x, bufXh, deg, gsum, gcnt, flag,
                                             n_nodes, n_graphs, ncvt);
    // (2) degree histogram + graph counts
    hist_count_kernel<<<eblocks, 256>>>(e_dst, deg, nbatch, gcnt, n_edges, n_nodes);
    // (3) single-kernel scan (rowptr + cursor)
    scan_lb_kernel<<<sblocks, SCAN_BLK>>>(deg, rowptr, cursor, agg, flag, n_nodes);
    // (4) CSR fill
    fill_kernel<<<eblocks, 256>>>(e_src, e_dst, cursor, csr, n_edges);

    // (5) P1/Q1 = x @ g1w1 halves
    gemm_pq<<<dim3(mb, 4), 256>>>(bufXh, g1w1, g1w1 + 64 * 128, g1b1,
                                  bufPh, bufQh, n_nodes, 128, 64, 64, 128);
    // (6) S1 = mean_dst relu(P1[dst] + Q1[src])
    gather_warp_kernel<128><<<gblocks, 256>>>(bufPh, bufQh, rowptr, deg, csr, bufSh, n_nodes);
    // (7) fused: H1 (smem only) -> P2/Q2
    gemm_h1pq2<<<mb, 256>>>(bufSh, g1w2, g1b2, g2w1, g2b1, deg,
                            bufPh, bufQh, n_nodes);
    // (8) S2
    gather_warp_kernel<64><<<gblocks, 256>>>(bufPh, bufQh, rowptr, deg, csr, bufSh, n_nodes);
    // (9) H2 = mask(S2 @ g2w2 + b2), pooled into gsum
    gemm_h2pool<<<mb, 256>>>(bufSh, g2w2, g2b2, deg, nbatch, gsum,
                             n_nodes, 64, 64, 64, 64);
    // (10) head
    head_kernel<<<n_graphs, 256>>>(state, gsum, gcnt,
                                   fc1_w, fc1_b, fc2_w, fc2_b,
                                   mean_w, mean_b, ls_w, ls_b,
                                   out, n_graphs);
}

// round 6
// speedup vs baseline: 1.8022x; 1.0357x over previous
#include <cuda_runtime.h>
#include <cuda_fp16.h>
#include <cstdint>

// ---------------------------------------------------------------------------
// Problem constants
// ---------------------------------------------------------------------------
#define MAX_NODES 50000
#define MAX_EDGES 800000
#define NODE_DIM  64
#define GNN_H     128
#define GNN_DIM   64
#define NB        128
#define HIDDEN    256
#define ACTION_DIM 8
#define SCAN_BLK  1024
#define SBLOCKS_MAX ((MAX_NODES + SCAN_BLK - 1) / SCAN_BLK)

// ---------------------------------------------------------------------------
// Device scratch
// ---------------------------------------------------------------------------
__device__ __half g_bufXh[MAX_NODES * NODE_DIM];
__device__ __half g_bufPh[MAX_NODES * GNN_H];
__device__ __half g_bufQh[MAX_NODES * GNN_H];
__device__ __half g_bufSh[MAX_NODES * GNN_H];
__device__ int    g_deg[MAX_NODES];
__device__ int    g_cursor[MAX_NODES];
__device__ int    g_rowptr[MAX_NODES];
__device__ int    g_csr[MAX_EDGES];
__device__ int    g_agg[SBLOCKS_MAX];
__device__ int    g_flag[SBLOCKS_MAX];
__device__ float  g_gsum[NB * GNN_DIM];
__device__ int    g_gcnt[NB];

// ---------------------------------------------------------------------------
// Side-stream chain: zero -> hist(4x ILP) -> scan -> fill(4x ILP)
// ---------------------------------------------------------------------------
__global__ void zero_side_kernel(int* __restrict__ deg, int* __restrict__ gcnt,
                                 int* __restrict__ flag, int n_nodes, int n_graphs)
{
    int i = blockIdx.x * blockDim.x + threadIdx.x;
    if (i < n_nodes) deg[i] = 0;
    if (i < n_graphs) gcnt[i] = 0;
    if (i < SBLOCKS_MAX) flag[i] = 0;
}

__global__ void hist_count4_kernel(const int* __restrict__ dst, int* __restrict__ deg,
                                   const int* __restrict__ nb, int* __restrict__ gcnt,
                                   int n_edges, int n_nodes)
{
    int t = blockIdx.x * blockDim.x + threadIdx.x;
    int base = t * 4;
    if (base + 3 < n_edges) {
        int4 d = *(const int4*)(dst + base);
        atomicAdd(&deg[d.x], 1);
        atomicAdd(&deg[d.y], 1);
        atomicAdd(&deg[d.z], 1);
        atomicAdd(&deg[d.w], 1);
    } else {
        for (int i = base; i < n_edges; i++) atomicAdd(&deg[dst[i]], 1);
    }
    if (base + 3 < n_nodes) {
        int4 b = *(const int4*)(nb + base);
        atomicAdd(&gcnt[b.x], 1);
        atomicAdd(&gcnt[b.y], 1);
        atomicAdd(&gcnt[b.z], 1);
        atomicAdd(&gcnt[b.w], 1);
    } else if (base < n_nodes) {
        for (int i = base; i < n_nodes; i++) atomicAdd(&gcnt[nb[i]], 1);
    }
}

// Single-kernel scan: block-local Hillis-Steele + warp-parallel lookback.
__global__ __launch_bounds__(SCAN_BLK) void scan_lb_kernel(
    const int* __restrict__ deg, int* __restrict__ rowptr, int* __restrict__ cursor,
    int* __restrict__ agg, int* __restrict__ flag, int n)
{
    __shared__ int sm[SCAN_BLK];
    __shared__ int s_run;
    int t = threadIdx.x, b = blockIdx.x;
    int i = b * SCAN_BLK + t;
    int v = (i < n) ? deg[i] : 0;
    sm[t] = v;
    __syncthreads();
    #pragma unroll
    for (int off = 1; off < SCAN_BLK; off <<= 1) {
        int u = (t >= off) ? sm[t - off] : 0;
        __syncthreads();
        sm[t] += u;
        __syncthreads();
    }
    if (t == 0) {
        agg[b] = sm[SCAN_BLK - 1];
        __threadfence();
        atomicExch(&flag[b], 1);
    }
    if (t < 32) {
        int run = 0;
        for (int j = t; j < b; j += 32) {
            while (atomicAdd(&flag[j], 0) == 0) { }
            __threadfence();
            run += *(volatile const int*)&agg[j];
        }
        #pragma unroll
        for (int off = 16; off; off >>= 1)
            run += __shfl_down_sync(0xffffffffu, run, off);
        if (t == 0) s_run = run;
    }
    __syncthreads();
    if (i < n) {
        int r = s_run + sm[t] - v;   // exclusive
        rowptr[i] = r;
        cursor[i] = r;
    }
}

__global__ void fill4_kernel(const int* __restrict__ src, const int* __restrict__ dst,
                             int* __restrict__ cursor, int* __restrict__ csr, int n_edges)
{
    int t = blockIdx.x * blockDim.x + threadIdx.x;
    int base = t * 4;
    if (base + 3 < n_edges) {
        int4 d = *(const int4*)(dst + base);
        int4 s = *(const int4*)(src + base);
        int p0 = atomicAdd(&cursor[d.x], 1);
        int p1 = atomicAdd(&cursor[d.y], 1);
        int p2 = atomicAdd(&cursor[d.z], 1);
        int p3 = atomicAdd(&cursor[d.w], 1);
        csr[p0] = s.x; csr[p1] = s.y; csr[p2] = s.z; csr[p3] = s.w;
    } else {
        for (int i = base; i < n_edges; i++) {
            int pos = atomicAdd(&cursor[dst[i]], 1);
            csr[pos] = src[i];
        }
    }
}

// ---------------------------------------------------------------------------
// Main-stream init: convert x to fp16 + zero gsum
// ---------------------------------------------------------------------------
__global__ void init_main_kernel(const float* __restrict__ x, __half* __restrict__ xh,
                                 float* __restrict__ gsum, int n_graphs, int ncvt)
{
    int i = blockIdx.x * blockDim.x + threadIdx.x;
    if (i < ncvt) {
        float4 v = ((const float4*)x)[i];
        uint2 o;
        *(__half2*)&o.x = __floats2half2_rn(v.x, v.y);
        *(__half2*)&o.y = __floats2half2_rn(v.z, v.w);
        ((uint2*)xh)[i] = o;
    }
    if (i < n_graphs * GNN_DIM) gsum[i] = 0.f;
}

// ---------------------------------------------------------------------------
// fp16 HMMA GEMM core: block tile 128x64, 8 warps 4x2, warp 32x32.
// ---------------------------------------------------------------------------
struct MmaCtx { int tid, g, ti, warp_m, warp_n; };

__device__ __forceinline__ MmaCtx make_ctx()
{
    MmaCtx c;
    c.tid = threadIdx.x;
    int lane = c.tid & 31;
    int wid  = c.tid >> 5;
    c.g = lane >> 2;
    c.ti = lane & 3;
    c.warp_m = wid & 3;
    c.warp_n = wid >> 2;
    return c;
}

__device__ __forceinline__ void mma16(float c[4], const uint32_t a[4], const uint32_t b[2])
{
    asm volatile(
        "mma.sync.aligned.m16n8k16.row.col.f32.f16.f16.f32 "
        "{%0,%1,%2,%3}, {%4,%5,%6,%7}, {%8,%9}, {%0,%1,%2,%3};"
        : "+f"(c[0]), "+f"(c[1]), "+f"(c[2]), "+f"(c[3])
        : "r"(a[0]), "r"(a[1]), "r"(a[2]), "r"(a[3]), "r"(b[0]), "r"(b[1]));
}

__device__ __forceinline__ void gemm_core_h(
    const __half* __restrict__ A, const float* __restrict__ W,
    int M, int K, int lda, int ldw, int bm, int bn,
    uint32_t (&As)[128][12], uint32_t (&Bs)[64][12],
    const MmaCtx& c, float acc[2][4][4])
{
    const int arow = c.tid >> 1;
    const int ac8  = (c.tid & 1) * 8;
    const int wr   = c.tid >> 4;
    const int wc   = (c.tid & 15) * 4;
    __half* bsh = (__half*)Bs;

    for (int kt = 0; kt < K; kt += 16) {
        {
            int grow = bm + arow;
            uint4 v = make_uint4(0u, 0u, 0u, 0u);
            if (grow < M) v = *(const uint4*)(A + (size_t)grow * lda + kt + ac8);
            *(uint4*)&As[arow][ac8 >> 1] = v;
        }
        {
            float4 v = *(const float4*)(W + (size_t)(kt + wr) * ldw + bn + wc);
            bsh[(wc + 0) * 24 + wr] = __float2half(v.x);
            bsh[(wc + 1) * 24 + wr] = __float2half(v.y);
            bsh[(wc + 2) * 24 + wr] = __float2half(v.z);
            bsh[(wc + 3) * 24 + wr] = __float2half(v.w);
        }
        __syncthreads();

        uint32_t a[2][4], b[4][2];
        #pragma unroll
        for (int mt = 0; mt < 2; mt++) {
            int r0 = c.warp_m * 32 + mt * 16 + c.g;
            a[mt][0] = As[r0][c.ti];
            a[mt][1] = As[r0 + 8][c.ti];
            a[mt][2] = As[r0][c.ti + 4];
            a[mt][3] = As[r0 + 8][c.ti + 4];
        }
        #pragma unroll
        for (int nt = 0; nt < 4; nt++) {
            int n = c.warp_n * 32 + nt * 8 + c.g;
            b[nt][0] = Bs[n][c.ti];
            b[nt][1] = Bs[n][c.ti + 4];
        }
        #pragma unroll
        for (int mt = 0; mt < 2; mt++)
            #pragma unroll
            for (int nt = 0; nt < 4; nt++)
                mma16(acc[mt][nt], a[mt], b[nt]);
        __syncthreads();
    }
}

// ---------------------------------------------------------------------------
// Layer-1 P/Q GEMM
// ---------------------------------------------------------------------------
__global__ __launch_bounds__(256) void gemm_pq(
    const __half* __restrict__ A,
    const float* __restrict__ Wp, const float* __restrict__ Wq,
    const float* __restrict__ biasp,
    __half* __restrict__ Ph, __half* __restrict__ Qh,
    int M, int N, int K, int lda, int ldw)
{
    __shared__ uint32_t As[128][12];
    __shared__ uint32_t Bs[64][12];

    MmaCtx c = make_ctx();
    const int ntile = N >> 6;
    const int is_q  = (blockIdx.y >= (unsigned)ntile);
    const int bn    = (blockIdx.y - (is_q ? ntile : 0)) * 64;
    const int bm    = blockIdx.x * 128;
    const float* W  = is_q ? Wq : Wp;
    __half* out     = is_q ? Qh : Ph;

    float acc[2][4][4] = {};
    gemm_core_h(A, W, M, K, lda, ldw, bm, bn, As, Bs, c, acc);

    #pragma unroll
    for (int mt = 0; mt < 2; mt++) {
        #pragma unroll
        for (int i = 0; i < 2; i++) {
            int row = bm + c.warp_m * 32 + mt * 16 + c.g + i * 8;
            if (row >= M) continue;
            #pragma unroll
            for (int nt = 0; nt < 4; nt++) {
                int col = bn + c.warp_n * 32 + nt * 8 + c.ti * 2;
                float v0 = acc[mt][nt][i * 2 + 0];
                float v1 = acc[mt][nt][i * 2 + 1];
                if (!is_q) { v0 += biasp[col]; v1 += biasp[col + 1]; }
                *(__half2*)(out + (size_t)row * N + col) = __floats2half2_rn(v0, v1);
            }
        }
    }
}

// ---------------------------------------------------------------------------
// FUSED: H1 (smem-only) -> P2/Q2
// ---------------------------------------------------------------------------
__global__ __launch_bounds__(256) void gemm_h1pq2(
    const __half* __restrict__ S,
    const float* __restrict__ W1, const float* __restrict__ b1,
    const float* __restrict__ W2, const float* __restrict__ b2,
    const int* __restrict__ deg,
    __half* __restrict__ P2, __half* __restrict__ Q2, int M)
{
    __shared__ uint32_t As[128][12];
    __shared__ uint32_t Bs[64][12];
    __shared__ uint32_t Ts[128][68];

    MmaCtx c = make_ctx();
    const int bm = blockIdx.x * 128;

    #pragma unroll
    for (int half = 0; half < 2; half++) {
        int bn = half * 64;
        float acc[2][4][4] = {};
        gemm_core_h(S, W1, M, 128, 128, 128, bm, bn, As, Bs, c, acc);
        #pragma unroll
        for (int mt = 0; mt < 2; mt++) {
            #pragma unroll
            for (int i = 0; i < 2; i++) {
                int row  = c.warp_m * 32 + mt * 16 + c.g + i * 8;
                int grow = bm + row;
                bool zero = (grow >= M) || (deg[grow < M ? grow : 0] == 0);
                #pragma unroll
                for (int nt = 0; nt < 4; nt++) {
                    int col = bn + c.warp_n * 32 + nt * 8 + c.ti * 2;
                    float v0 = acc[mt][nt][i * 2 + 0] + b1[col];
                    float v1 = acc[mt][nt][i * 2 + 1] + b1[col + 1];
                    v0 = fmaxf(v0, 0.f); v1 = fmaxf(v1, 0.f);
                    if (zero) { v0 = 0.f; v1 = 0.f; }
                    __half2 h = __floats2half2_rn(v0, v1);
                    Ts[row][col >> 1] = *(uint32_t*)&h;
                }
            }
        }
    }
    __syncthreads();

    const int wr = c.tid >> 4;
    const int wc = (c.tid & 15) * 4;
    __half* bsh = (__half*)Bs;

    #pragma unroll
    for (int half = 0; half < 2; half++) {
        const float* W = W2 + (size_t)half * 128 * 64;
        __half* out = half ? Q2 : P2;
        float acc[2][4][4] = {};
        for (int kt = 0; kt < 128; kt += 16) {
            {
                float4 v = *(const float4*)(W + (size_t)(kt + wr) * 64 + wc);
                bsh[(wc + 0) * 24 + wr] = __float2half(v.x);
                bsh[(wc + 1) * 24 + wr] = __float2half(v.y);
                bsh[(wc + 2) * 24 + wr] = __float2half(v.z);
                bsh[(wc + 3) * 24 + wr] = __float2half(v.w);
            }
            __syncthreads();
            uint32_t a[2][4], b[4][2];
            int kc = kt >> 1;
            #pragma unroll
            for (int mt = 0; mt < 2; mt++) {
                int r0 = c.warp_m * 32 + mt * 16 + c.g;
                a[mt][0] = Ts[r0][kc + c.ti];
                a[mt][1] = Ts[r0 + 8][kc + c.ti];
                a[mt][2] = Ts[r0][kc + c.ti + 4];
                a[mt][3] = Ts[r0 + 8][kc + c.ti + 4];
            }
            #pragma unroll
            for (int nt = 0; nt < 4; nt++) {
                int n = c.warp_n * 32 + nt * 8 + c.g;
                b[nt][0] = Bs[n][c.ti];
                b[nt][1] = Bs[n][c.ti + 4];
            }
            #pragma unroll
            for (int mt = 0; mt < 2; mt++)
                #pragma unroll
                for (int nt = 0; nt < 4; nt++)
                    mma16(acc[mt][nt], a[mt], b[nt]);
            __syncthreads();
        }
        #pragma unroll
        for (int mt = 0; mt < 2; mt++) {
            #pragma unroll
            for (int i = 0; i < 2; i++) {
                int row = bm + c.warp_m * 32 + mt * 16 + c.g + i * 8;
                if (row >= M) continue;
                #pragma unroll
                for (int nt = 0; nt < 4; nt++) {
                    int col = c.warp_n * 32 + nt * 8 + c.ti * 2;
                    float v0 = acc[mt][nt][i * 2 + 0];
                    float v1 = acc[mt][nt][i * 2 + 1];
                    if (!half) { v0 += b2[col]; v1 += b2[col + 1]; }
                    *(__half2*)(out + (size_t)row * 64 + col) = __floats2half2_rn(v0, v1);
                }
            }
        }
    }
}

// ---------------------------------------------------------------------------
// H2 GEMM with pooled epilogue
// ---------------------------------------------------------------------------
__global__ __launch_bounds__(256) void gemm_h2pool(
    const __half* __restrict__ A, const float* __restrict__ W,
    const float* __restrict__ bias, const int* __restrict__ deg,
    const int* __restrict__ nb, float* __restrict__ gsum,
    int M, int N, int K, int lda, int ldw)
{
    __shared__ uint32_t As[128][12];
    __shared__ uint32_t Bs[64][12];

    MmaCtx c = make_ctx();
    const int bm = blockIdx.x * 128;

    float acc[2][4][4] = {};
    gemm_core_h(A, W, M, K, lda, ldw, bm, 0, As, Bs, c, acc);

    #pragma unroll
    for (int mt = 0; mt < 2; mt++) {
        #pragma unroll
        for (int i = 0; i < 2; i++) {
            int row = bm + c.warp_m * 32 + mt * 16 + c.g + i * 8;
            if (row >= M) continue;
            bool zero = (deg[row] == 0);
            int batch = nb[row];
            #pragma unroll
            for (int nt = 0; nt < 4; nt++) {
                int col = c.warp_n * 32 + nt * 8 + c.ti * 2;
                float v0 = acc[mt][nt][i * 2 + 0] + bias[col];
                float v1 = acc[mt][nt][i * 2 + 1] + bias[col + 1];
                if (zero) { v0 = 0.f; v1 = 0.f; }
                atomicAdd(&gsum[batch * GNN_DIM + col],     v0);
                atomicAdd(&gsum[batch * GNN_DIM + col + 1], v1);
            }
        }
    }
}

// ---------------------------------------------------------------------------
// Gather: warp-per-node (R5)
// ---------------------------------------------------------------------------
__device__ __forceinline__ __half2 h2add(__half2 a, __half2 b) { return __hadd2(a, b); }

template <int FEAT>
__global__ __launch_bounds__(256) void gather_warp_kernel(
    const __half* __restrict__ P, const __half* __restrict__ Q,
    const int* __restrict__ row_ptr, const int* __restrict__ deg,
    const int* __restrict__ csr, __half* __restrict__ S, int n_nodes)
{
    constexpr int HALFL = FEAT / 8;
    constexpr int SHIFT = (HALFL == 16) ? 4 : 3;
    constexpr int EPI   = 32 / HALFL;

    int node = (blockIdx.x * blockDim.x + threadIdx.x) >> 5;
    if (node >= n_nodes) return;
    int lane  = threadIdx.x & 31;
    int sub   = lane & (HALFL - 1);
    int eslot = lane >> SHIFT;

    uint4 pv = *(const uint4*)(P + (size_t)node * FEAT + sub * 8);
    __half2 p0 = *(__half2*)&pv.x, p1 = *(__half2*)&pv.y;
    __half2 p2 = *(__half2*)&pv.z, p3 = *(__half2*)&pv.w;

    const __half2 z2 = __float2half2_rn(0.f);
    __half2 a0 = z2, a1 = z2, a2 = z2, a3 = z2;

    int d     = deg[node];
    int start = row_ptr[node];

    for (int base = 0; base < d; base += 32) {
        int cnt = min(d - base, 32);
        int sidx = 0;
        if (lane < cnt) sidx = csr[start + base + lane];
        int iters = (cnt + EPI - 1) / EPI;

        int  i   = eslot;
        bool act = i < cnt;
        int  s   = __shfl_sync(0xffffffffu, sidx, i & 31);
        uint4 qv = make_uint4(0u, 0u, 0u, 0u);
        if (act) qv = *(const uint4*)(Q + (size_t)s * FEAT + sub * 8);

        for (int it = 1; it <= iters; it++) {
            int  i2   = it * EPI + eslot;
            bool act2 = i2 < cnt;
            int  s2   = __shfl_sync(0xffffffffu, sidx, i2 & 31);
            uint4 qn  = make_uint4(0u, 0u, 0u, 0u);
            if (act2) qn = *(const uint4*)(Q + (size_t)s2 * FEAT + sub * 8);
            if (act) {
                a0 = h2add(a0, __hmax2(h2add(p0, *(__half2*)&qv.x), z2));
                a1 = h2add(a1, __hmax2(h2add(p1, *(__half2*)&qv.y), z2));
                a2 = h2add(a2, __hmax2(h2add(p2, *(__half2*)&qv.z), z2));
                a3 = h2add(a3, __hmax2(h2add(p3, *(__half2*)&qv.w), z2));
            }
            qv = qn; act = act2;
        }
    }

    #pragma unroll
    for (int off = HALFL; off < 32; off <<= 1) {
        uint32_t u;
        u = __shfl_xor_sync(0xffffffffu, *(uint32_t*)&a0, off); a0 = h2add(a0, *(__half2*)&u);
        u = __shfl_xor_sync(0xffffffffu, *(uint32_t*)&a1, off); a1 = h2add(a1, *(__half2*)&u);
        u = __shfl_xor_sync(0xffffffffu, *(uint32_t*)&a2, off); a2 = h2add(a2, *(__half2*)&u);
        u = __shfl_xor_sync(0xffffffffu, *(uint32_t*)&a3, off); a3 = h2add(a3, *(__half2*)&u);
    }

    if (eslot == 0) {
        float inv = 1.0f / (float)(d > 0 ? d : 1);
        float2 f0 = __half22float2(a0), f1 = __half22float2(a1);
        float2 f2 = __half22float2(a2), f3 = __half22float2(a3);
        uint4 o;
        *(__half2*)&o.x = __floats2half2_rn(f0.x * inv, f0.y * inv);
        *(__half2*)&o.y = __floats2half2_rn(f1.x * inv, f1.y * inv);
        *(__half2*)&o.z = __floats2half2_rn(f2.x * inv, f2.y * inv);
        *(__half2*)&o.w = __floats2half2_rn(f3.x * inv, f3.y * inv);
        *(uint4*)(S + (size_t)node * FEAT + sub * 8) = o;
    }
}

// ---------------------------------------------------------------------------
// Actor head
// ---------------------------------------------------------------------------
__global__ __launch_bounds__(256) void head_kernel(
    const float* __restrict__ state,
    const float* __restrict__ gsum, const int* __restrict__ gcnt,
    const float* __restrict__ fc1_w, const float* __restrict__ fc1_b,
    const float* __restrict__ fc2_w, const float* __restrict__ fc2_b,
    const float* __restrict__ mean_w, const float* __restrict__ mean_b,
    const float* __restrict__ ls_w, const float* __restrict__ ls_b,
    float* __restrict__ out, int n_graphs)
{
    __shared__ float z[128];
    __shared__ float h1[256];
    __shared__ float h2[256];
    int b = blockIdx.x;
    int t = threadIdx.x;
    if (b >= n_graphs) return;

    if (t < 64) {
        z[t] = state[b * 64 + t];
    } else if (t < 128) {
        float c = fmaxf((float)gcnt[b], 1.f);
        z[t] = gsum[b * GNN_DIM + (t - 64)] / c;
    }
    __syncthreads();

    {
        float s = fc1_b[t];
        #pragma unroll 4
        for (int k = 0; k < 128; k++) s += z[k] * fc1_w[k * 256 + t];
        h1[t] = fmaxf(s, 0.f);
    }
    __syncthreads();
    {
        float s = fc2_b[t];
        #pragma unroll 4
        for (int k = 0; k < 256; k++) s += h1[k] * fc2_w[k * 256 + t];
        h2[t] = fmaxf(s, 0.f);
    }
    __syncthreads();

    if (t < ACTION_DIM) {
        float s = mean_b[t];
        #pragma unroll 4
        for (int k = 0; k < 256; k++) s += h2[k] * mean_w[k * ACTION_DIM + t];
        out[b * ACTION_DIM + t] = s;
    } else if (t < 2 * ACTION_DIM) {
        int j = t - ACTION_DIM;
        float s = ls_b[j];
        #pragma unroll 4
        for (int k = 0; k < 256; k++) s += h2[k] * ls_w[k * ACTION_DIM + j];
        s = fminf(fmaxf(s, -20.f), 2.f);
        out[n_graphs * ACTION_DIM + b * ACTION_DIM + j] = s;
    }
}

// ---------------------------------------------------------------------------
// Launch (two-stream capture: CSR chain overlaps cvt + L1 GEMM)
// ---------------------------------------------------------------------------
extern "C" void kernel_launch(void* const* d_in, const int* in_sizes, int n_in,
                              void* d_out, int out_size)
{
    const float* state  = (const float*)d_in[0];
    const float* x      = (const float*)d_in[1];
    const int*   eidx   = (const int*)  d_in[2];
    const int*   nbatch = (const int*)  d_in[3];
    const float* g1w1   = (const float*)d_in[4];
    const float* g1b1   = (const float*)d_in[5];
    const float* g1w2   = (const float*)d_in[6];
    const float* g1b2   = (const float*)d_in[7];
    const float* g2w1   = (const float*)d_in[8];
    const float* g2b1   = (const float*)d_in[9];
    const float* g2w2   = (const float*)d_in[10];
    const float* g2b2   = (const float*)d_in[11];
    const float* fc1_w  = (const float*)d_in[12];
    const float* fc1_b  = (const float*)d_in[13];
    const float* fc2_w  = (const float*)d_in[14];
    const float* fc2_b  = (const float*)d_in[15];
    const float* mean_w = (const float*)d_in[16];
    const float* mean_b = (const float*)d_in[17];
    const float* ls_w   = (const float*)d_in[18];
    const float* ls_b   = (const float*)d_in[19];
    float* out = (float*)d_out;

    const int n_graphs = in_sizes[0] / 64;
    const int n_nodes  = in_sizes[1] / NODE_DIM;
    const int n_edges  = in_sizes[2] / 2;
    const int* e_src = eidx;
    const int* e_dst = eidx + n_edges;

    __half *bufXh, *bufPh, *bufQh, *bufSh;
    float *gsum;
    int *deg, *cursor, *rowptr, *csr, *gcnt, *agg, *flag;
    cudaGetSymbolAddress((void**)&bufXh,  g_bufXh);
    cudaGetSymbolAddress((void**)&bufPh,  g_bufPh);
    cudaGetSymbolAddress((void**)&bufQh,  g_bufQh);
    cudaGetSymbolAddress((void**)&bufSh,  g_bufSh);
    cudaGetSymbolAddress((void**)&deg,    g_deg);
    cudaGetSymbolAddress((void**)&cursor, g_cursor);
    cudaGetSymbolAddress((void**)&rowptr, g_rowptr);
    cudaGetSymbolAddress((void**)&csr,    g_csr);
    cudaGetSymbolAddress((void**)&agg,    g_agg);
    cudaGetSymbolAddress((void**)&flag,   g_flag);
    cudaGetSymbolAddress((void**)&gsum,   g_gsum);
    cudaGetSymbolAddress((void**)&gcnt,   g_gcnt);

    // Lazily-created side stream + fork/join events (host resources only;
    // per-call device work is identical and deterministic).
    static cudaStream_t s_side = nullptr;
    static cudaEvent_t  s_ev0 = nullptr, s_ev1 = nullptr;
    if (!s_side) {
        cudaStreamCreateWithFlags(&s_side, cudaStreamNonBlocking);
        cudaEventCreateWithFlags(&s_ev0, cudaEventDisableTiming);
        cudaEventCreateWithFlags(&s_ev1, cudaEventDisableTiming);
    }

    const int ncvt = n_nodes * NODE_DIM / 4;
    const int mb = (n_nodes + 127) / 128;
    const int e4blocks = (n_edges / 4 + 256) / 256;
    const int sblocks = (n_nodes + SCAN_BLK - 1) / SCAN_BLK;
    const int gblocks = (n_nodes * 32 + 255) / 256;

    // ---- fork: CSR chain on side stream ----
    cudaEventRecord(s_ev0, 0);
    cudaStreamWaitEvent(s_side, s_ev0, 0);
    zero_side_kernel<<<(n_nodes + 255) / 256, 256, 0, s_side>>>(deg, gcnt, flag, n_nodes, n_graphs);
    hist_count4_kernel<<<e4blocks, 256, 0, s_side>>>(e_dst, deg, nbatch, gcnt, n_edges, n_nodes);
    scan_lb_kernel<<<sblocks, SCAN_BLK, 0, s_side>>>(deg, rowptr, cursor, agg, flag, n_nodes);
    fill4_kernel<<<e4blocks, 256, 0, s_side>>>(e_src, e_dst, cursor, csr, n_edges);
    cudaEventRecord(s_ev1, s_side);

    // ---- main stream: x cvt + L1 P/Q GEMM (independent of CSR) ----
    init_main_kernel<<<(ncvt + 255) / 256, 256>>>(x, bufXh, gsum, n_graphs, ncvt);
    gemm_pq<<<dim3(mb, 4), 256>>>(bufXh, g1w1, g1w1 + 64 * 128, g1b1,
                                  bufPh, bufQh, n_nodes, 128, 64, 64, 128);

    // ---- join ----
    cudaStreamWaitEvent(0, s_ev1, 0);

    gather_warp_kernel<128><<<gblocks, 256>>>(bufPh, bufQh, rowptr, deg, csr, bufSh, n_nodes);
    gemm_h1pq2<<<mb, 256>>>(bufSh, g1w2, g1b2, g2w1, g2b1, deg,
                            bufPh, bufQh, n_nodes);
    gather_warp_kernel<64><<<gblocks, 256>>>(bufPh, bufQh, rowptr, deg, csr, bufSh, n_nodes);
    gemm_h2pool<<<mb, 256>>>(bufSh, g2w2, g2b2, deg, nbatch, gsum,
                             n_nodes, 64, 64, 64, 64);
    head_kernel<<<n_graphs, 256>>>(state, gsum, gcnt,
                                   fc1_w, fc1_b, fc2_w, fc2_b,
                                   mean_w, mean_b, ls_w, ls_b,
                                   out, n_graphs);
}